// round 6
// baseline (speedup 1.0000x reference)
#include <cuda_runtime.h>
#include <cuda_fp16.h>
#include <math.h>
#include <stdint.h>

#define B 2
#define S 2048
#define D 2048
#define NH 16
#define HD 128
#define M_ROWS (B * S)
#define N_QKV (3 * D)

// Scratch (allocation-free rule: __device__ globals), fp16 operands
__device__ __half g_xh[(size_t)M_ROWS * D];
__device__ __half g_wh[4][(size_t)D * D];
__device__ __half g_qkv[(size_t)M_ROWS * N_QKV];   // interleaved Q|K|V per row
__device__ __half g_oh[(size_t)M_ROWS * D];
__device__ float  g_bias[N_QKV];

// ---------------------------------------------------------------------------
// primitives
// ---------------------------------------------------------------------------
__device__ __forceinline__ void cpa16(uint32_t saddr, const void* gptr) {
    asm volatile("cp.async.cg.shared.global [%0], [%1], 16;\n"
                 :: "r"(saddr), "l"(gptr));
}
#define CP_COMMIT asm volatile("cp.async.commit_group;\n")
#define CP_WAIT(n) asm volatile("cp.async.wait_group %0;\n" :: "n"(n))

__device__ __forceinline__ void ldm_x4(uint32_t* r, uint32_t a) {
    asm volatile("ldmatrix.sync.aligned.m8n8.x4.shared.b16 {%0,%1,%2,%3}, [%4];"
                 : "=r"(r[0]), "=r"(r[1]), "=r"(r[2]), "=r"(r[3]) : "r"(a));
}
__device__ __forceinline__ void ldm_x4t(uint32_t* r, uint32_t a) {
    asm volatile("ldmatrix.sync.aligned.m8n8.x4.trans.shared.b16 {%0,%1,%2,%3}, [%4];"
                 : "=r"(r[0]), "=r"(r[1]), "=r"(r[2]), "=r"(r[3]) : "r"(a));
}
__device__ __forceinline__ void mma_f16(float* c, const uint32_t* a,
                                        uint32_t b0, uint32_t b1) {
    asm volatile(
        "mma.sync.aligned.m16n8k16.row.col.f32.f16.f16.f32 "
        "{%0,%1,%2,%3},{%4,%5,%6,%7},{%8,%9},{%0,%1,%2,%3};\n"
        : "+f"(c[0]), "+f"(c[1]), "+f"(c[2]), "+f"(c[3])
        : "r"(a[0]), "r"(a[1]), "r"(a[2]), "r"(a[3]), "r"(b0), "r"(b1));
}

// ---------------------------------------------------------------------------
// f32 -> f16 conversion; bias concat
// ---------------------------------------------------------------------------
__global__ void conv_h(const float* __restrict__ src, __half* __restrict__ dst, int n4) {
    int i = blockIdx.x * 256 + threadIdx.x;
    if (i < n4) {
        float4 v = ((const float4*)src)[i];
        __half2 h0 = __floats2half2_rn(v.x, v.y);
        __half2 h1 = __floats2half2_rn(v.z, v.w);
        ((uint2*)dst)[i] = make_uint2(*(uint32_t*)&h0, *(uint32_t*)&h1);
    }
}

__global__ void concat_bias(const float* __restrict__ bq, const float* __restrict__ bk,
                            const float* __restrict__ bv, float* __restrict__ dst) {
    int i = blockIdx.x * 256 + threadIdx.x;
    if (i < D) dst[i] = bq[i];
    else if (i < 2 * D) dst[i] = bk[i - D];
    else if (i < 3 * D) dst[i] = bv[i - 2 * D];
}

// ---------------------------------------------------------------------------
// fp16 GEMM: C[M, Ntot] = A[M,K=2048] @ W[Ntot,K]^T + bias. fp32 accumulate.
// CTA 128x256, 8 warps (64x64), BK=64 halves, 4-stage cp.async, 1 sync/iter.
// smem stage s at s*49152: A 128x128B, B 256x128B at +16384. (192 KB)
// ---------------------------------------------------------------------------
#define GEMM_SMEM_BYTES (4 * 49152)

__global__ __launch_bounds__(256) void gemm_f16(
    const __half* __restrict__ A, const __half* __restrict__ Wt,
    const float* __restrict__ bias, __half* __restrict__ Ch,
    float* __restrict__ Cf, int out_f32, int ldc)
{
    extern __shared__ char smg[];
    const uint32_t sb = (uint32_t)__cvta_generic_to_shared(smg);
    const int tid = threadIdx.x, lane = tid & 31, w = tid >> 5;
    const int g = lane >> 2, tig = lane & 3;
    const int wm = w >> 2, wn = w & 3;
    const int bm = blockIdx.y * 128, bn = blockIdx.x * 256;

    const int tl = lane >> 3, lr = lane & 7;
    const int rowoff = ((tl & 1) << 3) + lr;
    const int kadd = tl >> 1;
    const int fro = tid >> 3, fc16 = tid & 7;

    float acc[4][8][4];
#pragma unroll
    for (int mt = 0; mt < 4; ++mt)
#pragma unroll
        for (int nt = 0; nt < 8; ++nt)
#pragma unroll
            for (int e = 0; e < 4; ++e) acc[mt][nt][e] = 0.f;

#define GF(st, kt)                                                              \
    do {                                                                        \
        const int k0h = (kt) * 64;                                              \
        _Pragma("unroll")                                                       \
        for (int i = 0; i < 4; ++i) {                                           \
            int row = fro + 32 * i;                                             \
            cpa16(sb + (st) * 49152 + row * 128 + ((fc16 ^ (row & 7)) << 4),    \
                  A + (size_t)(bm + row) * D + k0h + fc16 * 8);                 \
        }                                                                       \
        _Pragma("unroll")                                                       \
        for (int i = 0; i < 8; ++i) {                                           \
            int row = fro + 32 * i;                                             \
            cpa16(sb + (st) * 49152 + 16384 + row * 128                         \
                      + ((fc16 ^ (row & 7)) << 4),                              \
                  Wt + (size_t)(bn + row) * D + k0h + fc16 * 8);                \
        }                                                                       \
    } while (0)

    GF(0, 0); CP_COMMIT;
    GF(1, 1); CP_COMMIT;
    GF(2, 2); CP_COMMIT;

    for (int kt = 0; kt < 32; ++kt) {
        CP_WAIT(2);
        __syncthreads();
        if (kt + 3 < 32) { GF((kt + 3) & 3, kt + 3); }
        CP_COMMIT;
        const uint32_t as = sb + (kt & 3) * 49152;
        const uint32_t bs = as + 16384;
#pragma unroll
        for (int ks = 0; ks < 4; ++ks) {
            const int c16 = 2 * ks + kadd;
            uint32_t af[4][4], bf[4][4];
#pragma unroll
            for (int mt = 0; mt < 4; ++mt) {
                int row = wm * 64 + mt * 16 + rowoff;
                ldm_x4(af[mt], as + row * 128 + ((c16 ^ (row & 7)) << 4));
            }
#pragma unroll
            for (int np = 0; np < 4; ++np) {
                int row = wn * 64 + np * 16 + rowoff;
                ldm_x4(bf[np], bs + row * 128 + ((c16 ^ (row & 7)) << 4));
            }
#pragma unroll
            for (int mt = 0; mt < 4; ++mt)
#pragma unroll
                for (int np = 0; np < 4; ++np) {
                    mma_f16(acc[mt][2 * np],     af[mt], bf[np][0], bf[np][2]);
                    mma_f16(acc[mt][2 * np + 1], af[mt], bf[np][1], bf[np][3]);
                }
        }
    }

    // epilogue
#pragma unroll
    for (int mt = 0; mt < 4; ++mt) {
        int r0 = bm + wm * 64 + mt * 16 + g;
#pragma unroll
        for (int nt = 0; nt < 8; ++nt) {
            int c = bn + wn * 64 + nt * 8 + 2 * tig;
            float b0 = bias[c], b1 = bias[c + 1];
            float v00 = acc[mt][nt][0] + b0, v01 = acc[mt][nt][1] + b1;
            float v10 = acc[mt][nt][2] + b0, v11 = acc[mt][nt][3] + b1;
            if (out_f32) {
                *(float2*)(Cf + (size_t)r0 * ldc + c) = make_float2(v00, v01);
                *(float2*)(Cf + (size_t)(r0 + 8) * ldc + c) = make_float2(v10, v11);
            } else {
                __half2 h0 = __floats2half2_rn(v00, v01);
                __half2 h1 = __floats2half2_rn(v10, v11);
                *(__half2*)(Ch + (size_t)r0 * ldc + c) = h0;
                *(__half2*)(Ch + (size_t)(r0 + 8) * ldc + c) = h1;
            }
        }
    }
#undef GF
}

// ---------------------------------------------------------------------------
// Fused RMSNorm (full D, fp32 math) * g + per-head RoPE, in place on fp16
// rows of stride ld.
// ---------------------------------------------------------------------------
__global__ __launch_bounds__(256) void rmsnorm_rope_h(
    __half* __restrict__ t, const float* __restrict__ gw,
    const float* __restrict__ freqs, int ld)
{
    const int row = blockIdx.x;
    const int s = row & (S - 1);
    const int tid = threadIdx.x;
    __half* p = t + (size_t)row * ld;

    uint4 raw = *(const uint4*)(p + tid * 8);
    __half2 h[4] = { *(__half2*)&raw.x, *(__half2*)&raw.y,
                     *(__half2*)&raw.z, *(__half2*)&raw.w };
    float u[8];
#pragma unroll
    for (int j = 0; j < 4; ++j) {
        float2 f = __half22float2(h[j]);
        u[2 * j] = f.x; u[2 * j + 1] = f.y;
    }
    float ss = 0.f;
#pragma unroll
    for (int j = 0; j < 8; ++j) ss += u[j] * u[j];

    __shared__ float red[256];
    red[tid] = ss;
    __syncthreads();
    for (int off = 128; off > 0; off >>= 1) {
        if (tid < off) red[tid] += red[tid + off];
        __syncthreads();
    }
    const float inv = rsqrtf(red[0] / (float)D + 1e-6f);

    float4 g0 = *(const float4*)(gw + tid * 8);
    float4 g1 = *(const float4*)(gw + tid * 8 + 4);
    u[0] *= inv * g0.x; u[1] *= inv * g0.y; u[2] *= inv * g0.z; u[3] *= inv * g0.w;
    u[4] *= inv * g1.x; u[5] *= inv * g1.y; u[6] *= inv * g1.z; u[7] *= inv * g1.w;

    uint4 outw;
    uint32_t* ow = (uint32_t*)&outw;
#pragma unroll
    for (int j = 0; j < 4; ++j) {
        int pidx = tid * 4 + j;
        int i = pidx & 63;
        float sn, cs;
        sincosf(freqs[(size_t)s * 64 + i], &sn, &cs);
        float re = u[2 * j], im = u[2 * j + 1];
        __half2 hv = __floats2half2_rn(re * cs - im * sn, re * sn + im * cs);
        ow[j] = *(uint32_t*)&hv;
    }
    *(uint4*)(p + tid * 8) = outw;
}

// ---------------------------------------------------------------------------
// Flash attention fp16: CTA = 128 q rows x (b,h), 8 warps x 16 rows.
// Q frags from gmem into regs. K,V 3-stage cp.async (64 kv rows), 1 sync/iter.
// smem: K [0,49152) 3 stages, V [49152,98304), P [98304,114688).
// QKV rows have stride N_QKV (interleaved buffer).
// ---------------------------------------------------------------------------
#define FA_SMEM_BYTES 114688

__global__ __launch_bounds__(256) void flash_f16(
    const __half* __restrict__ QKV, const int* __restrict__ seq_lens,
    __half* __restrict__ Og)
{
    extern __shared__ char smf[];
    const uint32_t sb = (uint32_t)__cvta_generic_to_shared(smf);
    const int tid = threadIdx.x, lane = tid & 31, w = tid >> 5;
    const int g = lane >> 2, tig = lane & 3;
    const int bh = blockIdx.y, b = bh >> 4, h = bh & 15;
    const int q0 = blockIdx.x * 128;
    const int len = seq_lens[b];
    const float scale = 0.088388347648318447f;  // 1/sqrt(128)

    const __half* Qb = QKV + (size_t)b * S * N_QKV + h * HD;
    const __half* Kb = Qb + D;
    const __half* Vb = Qb + 2 * D;

    const int tl = lane >> 3, lr = lane & 7;
    const int rowoff = ((tl & 1) << 3) + lr;
    const int kadd = tl >> 1;
    const int fro = tid >> 4, fc16 = tid & 15;

#define KV_FILL(st, j0)                                                         \
    do {                                                                        \
        _Pragma("unroll")                                                       \
        for (int i = 0; i < 4; ++i) {                                           \
            int row = fro + 16 * i;                                             \
            uint32_t soff = (uint32_t)(row * 256 + ((fc16 ^ (row & 7)) << 4));  \
            cpa16(sb + (st) * 16384 + soff,                                     \
                  Kb + (size_t)((j0) + row) * N_QKV + fc16 * 8);                \
            cpa16(sb + 49152 + (st) * 16384 + soff,                             \
                  Vb + (size_t)((j0) + row) * N_QKV + fc16 * 8);                \
        }                                                                       \
    } while (0)

    KV_FILL(0, 0);  CP_COMMIT;
    KV_FILL(1, 64); CP_COMMIT;

    // Q fragments direct from gmem (rows w*16+g, w*16+g+8)
    uint32_t qf[8][4];
    {
        const __half* r0p = Qb + (size_t)(q0 + w * 16 + g) * N_QKV;
        const __half* r1p = r0p + (size_t)8 * N_QKV;
#pragma unroll
        for (int ks = 0; ks < 8; ++ks) {
            int c = ks * 16 + 2 * tig;
            qf[ks][0] = *(const uint32_t*)(r0p + c);
            qf[ks][1] = *(const uint32_t*)(r1p + c);
            qf[ks][2] = *(const uint32_t*)(r0p + c + 8);
            qf[ks][3] = *(const uint32_t*)(r1p + c + 8);
        }
    }

    float o[16][4];
#pragma unroll
    for (int nt = 0; nt < 16; ++nt)
#pragma unroll
        for (int e = 0; e < 4; ++e) o[nt][e] = 0.f;
    float m0 = -1e30f, m1 = -1e30f, l0 = 0.f, l1 = 0.f;

    const uint32_t pbase = sb + 98304;
    const int prA = w * 16 + g, prB = prA + 8;
    const uint32_t paddrA = pbase + prA * 128;
    const uint32_t paddrB = pbase + prB * 128;

    for (int t = 0; t < 32; ++t) {
        CP_WAIT(1);
        __syncthreads();
        if (t + 2 < 32) KV_FILL((t + 2) % 3, (t + 2) * 64);
        CP_COMMIT;
        const int st = t % 3;
        const uint32_t kst = sb + st * 16384;
        const uint32_t vst = sb + 49152 + st * 16384;

        // ---- S = Q @ K^T ----
        float s[8][4];
#pragma unroll
        for (int nt = 0; nt < 8; ++nt)
#pragma unroll
            for (int e = 0; e < 4; ++e) s[nt][e] = 0.f;
#pragma unroll
        for (int ks = 0; ks < 8; ++ks) {
            const int c16 = 2 * ks + kadd;
            uint32_t kb[4][4];
#pragma unroll
            for (int np = 0; np < 4; ++np) {
                int row = np * 16 + rowoff;
                ldm_x4(kb[np], kst + row * 256 + ((c16 ^ (row & 7)) << 4));
            }
#pragma unroll
            for (int np = 0; np < 4; ++np) {
                mma_f16(s[2 * np],     qf[ks], kb[np][0], kb[np][2]);
                mma_f16(s[2 * np + 1], qf[ks], kb[np][1], kb[np][3]);
            }
        }

        const int j0 = t * 64;
        if (j0 + 64 > len) {
#pragma unroll
            for (int nt = 0; nt < 8; ++nt) {
                int c = j0 + nt * 8 + 2 * tig;
                if (c     >= len) { s[nt][0] = -1e30f; s[nt][2] = -1e30f; }
                if (c + 1 >= len) { s[nt][1] = -1e30f; s[nt][3] = -1e30f; }
            }
        }

        // ---- online softmax (rows g, g+8) ----
        float mx0 = -1e30f, mx1 = -1e30f;
#pragma unroll
        for (int nt = 0; nt < 8; ++nt) {
            mx0 = fmaxf(mx0, fmaxf(s[nt][0], s[nt][1]));
            mx1 = fmaxf(mx1, fmaxf(s[nt][2], s[nt][3]));
        }
        mx0 = fmaxf(mx0, __shfl_xor_sync(0xffffffffu, mx0, 1));
        mx0 = fmaxf(mx0, __shfl_xor_sync(0xffffffffu, mx0, 2));
        mx1 = fmaxf(mx1, __shfl_xor_sync(0xffffffffu, mx1, 1));
        mx1 = fmaxf(mx1, __shfl_xor_sync(0xffffffffu, mx1, 2));
        float mn0 = fmaxf(m0, mx0), mn1 = fmaxf(m1, mx1);
        float al0 = __expf(scale * (m0 - mn0));
        float al1 = __expf(scale * (m1 - mn1));
        float sum0 = 0.f, sum1 = 0.f;
#pragma unroll
        for (int nt = 0; nt < 8; ++nt) {
            s[nt][0] = __expf(scale * (s[nt][0] - mn0)); sum0 += s[nt][0];
            s[nt][1] = __expf(scale * (s[nt][1] - mn0)); sum0 += s[nt][1];
            s[nt][2] = __expf(scale * (s[nt][2] - mn1)); sum1 += s[nt][2];
            s[nt][3] = __expf(scale * (s[nt][3] - mn1)); sum1 += s[nt][3];
        }
        sum0 += __shfl_xor_sync(0xffffffffu, sum0, 1);
        sum0 += __shfl_xor_sync(0xffffffffu, sum0, 2);
        sum1 += __shfl_xor_sync(0xffffffffu, sum1, 1);
        sum1 += __shfl_xor_sync(0xffffffffu, sum1, 2);
        l0 = l0 * al0 + sum0; l1 = l1 * al1 + sum1;
        m0 = mn0; m1 = mn1;
#pragma unroll
        for (int nt = 0; nt < 16; ++nt) {
            o[nt][0] *= al0; o[nt][1] *= al0;
            o[nt][2] *= al1; o[nt][3] *= al1;
        }

        // ---- P -> per-warp smem (fp16) ----
#pragma unroll
        for (int nt = 0; nt < 8; ++nt) {
            __half2 hA = __floats2half2_rn(s[nt][0], s[nt][1]);
            __half2 hB = __floats2half2_rn(s[nt][2], s[nt][3]);
            uint32_t offA = ((nt ^ (prA & 7)) << 4) + 4 * tig;
            uint32_t offB = ((nt ^ (prB & 7)) << 4) + 4 * tig;
            *(uint32_t*)((char*)smf + (paddrA - sb) + offA) = *(uint32_t*)&hA;
            *(uint32_t*)((char*)smf + (paddrB - sb) + offB) = *(uint32_t*)&hB;
        }
        __syncwarp();

        // ---- O += P @ V ----
#pragma unroll
        for (int ks = 0; ks < 4; ++ks) {
            uint32_t pa[4];
            {
                int row = w * 16 + rowoff;
                int c16 = 2 * ks + kadd;
                ldm_x4(pa, pbase + row * 128 + ((c16 ^ (row & 7)) << 4));
            }
#pragma unroll
            for (int np = 0; np < 8; ++np) {
                uint32_t vb[4];
                int row = ks * 16 + rowoff;
                int c16 = 2 * np + kadd;
                ldm_x4t(vb, vst + row * 256 + ((c16 ^ (row & 7)) << 4));
                mma_f16(o[2 * np],     pa, vb[0], vb[1]);
                mma_f16(o[2 * np + 1], pa, vb[2], vb[3]);
            }
        }
    }

    // ---- epilogue: normalize, store fp16 (row stride D) ----
    float li0 = 1.0f / l0, li1 = 1.0f / l1;
    __half* ObA = Og + (size_t)(b * S + q0 + w * 16 + g) * D + h * HD;
    __half* ObB = ObA + (size_t)8 * D;
#pragma unroll
    for (int nt = 0; nt < 16; ++nt) {
        int c = nt * 8 + 2 * tig;
        __half2 h0 = __floats2half2_rn(o[nt][0] * li0, o[nt][1] * li0);
        __half2 h1 = __floats2half2_rn(o[nt][2] * li1, o[nt][3] * li1);
        *(__half2*)(ObA + c) = h0;
        *(__half2*)(ObB + c) = h1;
    }
#undef KV_FILL
}

// ---------------------------------------------------------------------------
extern "C" void kernel_launch(void* const* d_in, const int* in_sizes, int n_in,
                              void* d_out, int out_size) {
    (void)in_sizes; (void)n_in; (void)out_size;
    const float* x        = (const float*)d_in[0];
    const int*   seq_lens = (const int*)  d_in[1];
    const float* freqs    = (const float*)d_in[2];
    const float* wq       = (const float*)d_in[3];
    const float* bq       = (const float*)d_in[4];
    const float* wk       = (const float*)d_in[5];
    const float* bk       = (const float*)d_in[6];
    const float* wv       = (const float*)d_in[7];
    const float* bv       = (const float*)d_in[8];
    const float* wo       = (const float*)d_in[9];
    const float* bo       = (const float*)d_in[10];
    const float* gq       = (const float*)d_in[11];
    const float* gk       = (const float*)d_in[12];
    float* out = (float*)d_out;

    __half *pxh, *pwh, *pqkv, *po;
    float* pbias;
    cudaGetSymbolAddress((void**)&pxh, g_xh);
    cudaGetSymbolAddress((void**)&pwh, g_wh);
    cudaGetSymbolAddress((void**)&pqkv, g_qkv);
    cudaGetSymbolAddress((void**)&po, g_oh);
    cudaGetSymbolAddress((void**)&pbias, g_bias);
    __half* pw0 = pwh;                          // wq
    __half* pw1 = pwh + (size_t)D * D;          // wk
    __half* pw2 = pwh + 2 * (size_t)D * D;      // wv
    __half* pw3 = pwh + 3 * (size_t)D * D;      // wo

    cudaFuncSetAttribute(gemm_f16, cudaFuncAttributeMaxDynamicSharedMemorySize,
                         GEMM_SMEM_BYTES);
    cudaFuncSetAttribute(flash_f16, cudaFuncAttributeMaxDynamicSharedMemorySize,
                         FA_SMEM_BYTES);

    conv_h<<<(M_ROWS * D / 4 + 255) / 256, 256>>>(x, pxh, M_ROWS * D / 4);
    conv_h<<<(D * D / 4 + 255) / 256, 256>>>(wq, pw0, D * D / 4);
    conv_h<<<(D * D / 4 + 255) / 256, 256>>>(wk, pw1, D * D / 4);
    conv_h<<<(D * D / 4 + 255) / 256, 256>>>(wv, pw2, D * D / 4);
    conv_h<<<(D * D / 4 + 255) / 256, 256>>>(wo, pw3, D * D / 4);
    concat_bias<<<N_QKV / 256, 256>>>(bq, bk, bv, pbias);

    // Fused QKV projection: N = 6144, output interleaved with row stride 6144
    gemm_f16<<<dim3(N_QKV / 256, M_ROWS / 128), 256, GEMM_SMEM_BYTES>>>(
        pxh, pw0, pbias, pqkv, nullptr, 0, N_QKV);

    rmsnorm_rope_h<<<M_ROWS, 256>>>(pqkv,     gq, freqs, N_QKV);       // Q
    rmsnorm_rope_h<<<M_ROWS, 256>>>(pqkv + D, gk, freqs, N_QKV);       // K

    flash_f16<<<dim3(S / 128, B * NH), 256, FA_SMEM_BYTES>>>(
        pqkv, seq_lens, po);

    gemm_f16<<<dim3(D / 256, M_ROWS / 128), 256, GEMM_SMEM_BYTES>>>(
        po, pw3, bo, nullptr, out, 1, D);
}

// round 8
// speedup vs baseline: 1.0123x; 1.0123x over previous
#include <cuda_runtime.h>
#include <cuda_fp16.h>
#include <math.h>
#include <stdint.h>

#define B 2
#define S 2048
#define D 2048
#define NH 16
#define HD 128
#define M_ROWS (B * S)
#define N_QKV (3 * D)

// Scratch (allocation-free rule: __device__ globals), fp16 operands
__device__ __half g_xh[(size_t)M_ROWS * D];
__device__ __half g_wh[4][(size_t)D * D];
__device__ __half g_qkv[(size_t)M_ROWS * N_QKV];   // interleaved Q|K|V per row
__device__ __half g_oh[(size_t)M_ROWS * D];
__device__ float  g_bias[N_QKV];

// ---------------------------------------------------------------------------
// primitives
// ---------------------------------------------------------------------------
__device__ __forceinline__ void cpa16(uint32_t saddr, const void* gptr) {
    asm volatile("cp.async.cg.shared.global [%0], [%1], 16;\n"
                 :: "r"(saddr), "l"(gptr));
}
#define CP_COMMIT asm volatile("cp.async.commit_group;\n")
#define CP_WAIT(n) asm volatile("cp.async.wait_group %0;\n" :: "n"(n))

__device__ __forceinline__ void ldm_x4(uint32_t* r, uint32_t a) {
    asm volatile("ldmatrix.sync.aligned.m8n8.x4.shared.b16 {%0,%1,%2,%3}, [%4];"
                 : "=r"(r[0]), "=r"(r[1]), "=r"(r[2]), "=r"(r[3]) : "r"(a));
}
__device__ __forceinline__ void ldm_x4t(uint32_t* r, uint32_t a) {
    asm volatile("ldmatrix.sync.aligned.m8n8.x4.trans.shared.b16 {%0,%1,%2,%3}, [%4];"
                 : "=r"(r[0]), "=r"(r[1]), "=r"(r[2]), "=r"(r[3]) : "r"(a));
}
__device__ __forceinline__ void mma_f16(float* c, const uint32_t* a,
                                        uint32_t b0, uint32_t b1) {
    asm volatile(
        "mma.sync.aligned.m16n8k16.row.col.f32.f16.f16.f32 "
        "{%0,%1,%2,%3},{%4,%5,%6,%7},{%8,%9},{%0,%1,%2,%3};\n"
        : "+f"(c[0]), "+f"(c[1]), "+f"(c[2]), "+f"(c[3])
        : "r"(a[0]), "r"(a[1]), "r"(a[2]), "r"(a[3]), "r"(b0), "r"(b1));
}

// ---------------------------------------------------------------------------
// conversions (kept to 2 launches so flash lands at capture index 4)
// ---------------------------------------------------------------------------
__global__ void conv_h(const float* __restrict__ src, __half* __restrict__ dst, int n4) {
    int i = blockIdx.x * 256 + threadIdx.x;
    if (i < n4) {
        float4 v = ((const float4*)src)[i];
        __half2 h0 = __floats2half2_rn(v.x, v.y);
        __half2 h1 = __floats2half2_rn(v.z, v.w);
        ((uint2*)dst)[i] = make_uint2(*(uint32_t*)&h0, *(uint32_t*)&h1);
    }
}

// all 4 weights -> g_wh, plus qkv bias concat, in one launch
__global__ void conv_w4(const float* __restrict__ w0, const float* __restrict__ w1,
                        const float* __restrict__ w2, const float* __restrict__ w3,
                        const float* __restrict__ bq, const float* __restrict__ bk,
                        const float* __restrict__ bv,
                        __half* __restrict__ dst, float* __restrict__ bias_dst) {
    const int per = D * D / 4;
    int i = blockIdx.x * 256 + threadIdx.x;
    if (i < 4 * per) {
        int which = i / per, j = i - which * per;
        const float* src = (which == 0) ? w0 : (which == 1) ? w1
                         : (which == 2) ? w2 : w3;
        float4 v = ((const float4*)src)[j];
        __half2 h0 = __floats2half2_rn(v.x, v.y);
        __half2 h1 = __floats2half2_rn(v.z, v.w);
        ((uint2*)dst)[i] = make_uint2(*(uint32_t*)&h0, *(uint32_t*)&h1);
    } else {
        int j = i - 4 * per;
        if (j < N_QKV)
            bias_dst[j] = (j < D) ? bq[j] : (j < 2 * D) ? bk[j - D] : bv[j - 2 * D];
    }
}

// ---------------------------------------------------------------------------
// fp16 GEMM: C[M, Ntot] = A @ W^T + bias. CTA 128x256, 8 warps (64x64),
// BK=64, 4-stage cp.async, 1 sync/iter, register-double-buffered fragments.
// ---------------------------------------------------------------------------
#define GEMM_SMEM_BYTES (4 * 49152)

__global__ __launch_bounds__(256) void gemm_f16(
    const __half* __restrict__ A, const __half* __restrict__ Wt,
    const float* __restrict__ bias, __half* __restrict__ Ch,
    float* __restrict__ Cf, int out_f32, int ldc)
{
    extern __shared__ char smg[];
    const uint32_t sb = (uint32_t)__cvta_generic_to_shared(smg);
    const int tid = threadIdx.x, lane = tid & 31, w = tid >> 5;
    const int g = lane >> 2, tig = lane & 3;
    const int wm = w >> 2, wn = w & 3;
    const int bm = blockIdx.y * 128, bn = blockIdx.x * 256;

    const int tl = lane >> 3, lr = lane & 7;
    const int rowoff = ((tl & 1) << 3) + lr;
    const int kadd = tl >> 1;
    const int fro = tid >> 3, fc16 = tid & 7;

    float acc[4][8][4];
#pragma unroll
    for (int mt = 0; mt < 4; ++mt)
#pragma unroll
        for (int nt = 0; nt < 8; ++nt)
#pragma unroll
            for (int e = 0; e < 4; ++e) acc[mt][nt][e] = 0.f;

#define GF(st, kt)                                                              \
    do {                                                                        \
        const int k0h = (kt) * 64;                                              \
        _Pragma("unroll")                                                       \
        for (int i = 0; i < 4; ++i) {                                           \
            int row = fro + 32 * i;                                             \
            cpa16(sb + (st) * 49152 + row * 128 + ((fc16 ^ (row & 7)) << 4),    \
                  A + (size_t)(bm + row) * D + k0h + fc16 * 8);                 \
        }                                                                       \
        _Pragma("unroll")                                                       \
        for (int i = 0; i < 8; ++i) {                                           \
            int row = fro + 32 * i;                                             \
            cpa16(sb + (st) * 49152 + 16384 + row * 128                         \
                      + ((fc16 ^ (row & 7)) << 4),                              \
                  Wt + (size_t)(bn + row) * D + k0h + fc16 * 8);                \
        }                                                                       \
    } while (0)

#define LD_FRAGS(buf, as, bs, ks)                                               \
    do {                                                                        \
        const int c16 = 2 * (ks) + kadd;                                        \
        _Pragma("unroll")                                                       \
        for (int mt = 0; mt < 4; ++mt) {                                        \
            int row = wm * 64 + mt * 16 + rowoff;                               \
            ldm_x4(af[buf][mt], (as) + row * 128 + ((c16 ^ (row & 7)) << 4));   \
        }                                                                       \
        _Pragma("unroll")                                                       \
        for (int np = 0; np < 4; ++np) {                                        \
            int row = wn * 64 + np * 16 + rowoff;                               \
            ldm_x4(bf[buf][np], (bs) + row * 128 + ((c16 ^ (row & 7)) << 4));   \
        }                                                                       \
    } while (0)

    GF(0, 0); CP_COMMIT;
    GF(1, 1); CP_COMMIT;
    GF(2, 2); CP_COMMIT;

    uint32_t af[2][4][4], bf[2][4][4];

    for (int kt = 0; kt < 32; ++kt) {
        CP_WAIT(2);
        __syncthreads();
        if (kt + 3 < 32) { GF((kt + 3) & 3, kt + 3); }
        CP_COMMIT;
        const uint32_t as = sb + (kt & 3) * 49152;
        const uint32_t bs = as + 16384;
        LD_FRAGS(0, as, bs, 0);
#pragma unroll
        for (int ks = 0; ks < 4; ++ks) {
            const int kc = ks & 1;
            if (ks < 3) LD_FRAGS(kc ^ 1, as, bs, ks + 1);
#pragma unroll
            for (int mt = 0; mt < 4; ++mt)
#pragma unroll
                for (int np = 0; np < 4; ++np) {
                    mma_f16(acc[mt][2 * np],     af[kc][mt], bf[kc][np][0], bf[kc][np][2]);
                    mma_f16(acc[mt][2 * np + 1], af[kc][mt], bf[kc][np][1], bf[kc][np][3]);
                }
        }
    }

    // epilogue
#pragma unroll
    for (int mt = 0; mt < 4; ++mt) {
        int r0 = bm + wm * 64 + mt * 16 + g;
#pragma unroll
        for (int nt = 0; nt < 8; ++nt) {
            int c = bn + wn * 64 + nt * 8 + 2 * tig;
            float b0 = bias[c], b1 = bias[c + 1];
            float v00 = acc[mt][nt][0] + b0, v01 = acc[mt][nt][1] + b1;
            float v10 = acc[mt][nt][2] + b0, v11 = acc[mt][nt][3] + b1;
            if (out_f32) {
                *(float2*)(Cf + (size_t)r0 * ldc + c) = make_float2(v00, v01);
                *(float2*)(Cf + (size_t)(r0 + 8) * ldc + c) = make_float2(v10, v11);
            } else {
                __half2 h0 = __floats2half2_rn(v00, v01);
                __half2 h1 = __floats2half2_rn(v10, v11);
                *(__half2*)(Ch + (size_t)r0 * ldc + c) = h0;
                *(__half2*)(Ch + (size_t)(r0 + 8) * ldc + c) = h1;
            }
        }
    }
#undef GF
#undef LD_FRAGS
}

// ---------------------------------------------------------------------------
// Fused RMSNorm+RoPE for BOTH Q and K in one launch (blockIdx.y selects).
// ---------------------------------------------------------------------------
__global__ __launch_bounds__(256) void rmsnorm_rope_h(
    __half* __restrict__ qkv, const float* __restrict__ gq,
    const float* __restrict__ gk, const float* __restrict__ freqs)
{
    const int row = blockIdx.x;
    const int s = row & (S - 1);
    const int tid = threadIdx.x;
    const float* gw = blockIdx.y ? gk : gq;
    __half* p = qkv + (size_t)row * N_QKV + blockIdx.y * D;

    uint4 raw = *(const uint4*)(p + tid * 8);
    __half2 h[4] = { *(__half2*)&raw.x, *(__half2*)&raw.y,
                     *(__half2*)&raw.z, *(__half2*)&raw.w };
    float u[8];
#pragma unroll
    for (int j = 0; j < 4; ++j) {
        float2 f = __half22float2(h[j]);
        u[2 * j] = f.x; u[2 * j + 1] = f.y;
    }
    float ss = 0.f;
#pragma unroll
    for (int j = 0; j < 8; ++j) ss += u[j] * u[j];

    __shared__ float red[256];
    red[tid] = ss;
    __syncthreads();
    for (int off = 128; off > 0; off >>= 1) {
        if (tid < off) red[tid] += red[tid + off];
        __syncthreads();
    }
    const float inv = rsqrtf(red[0] / (float)D + 1e-6f);

    float4 g0 = *(const float4*)(gw + tid * 8);
    float4 g1 = *(const float4*)(gw + tid * 8 + 4);
    u[0] *= inv * g0.x; u[1] *= inv * g0.y; u[2] *= inv * g0.z; u[3] *= inv * g0.w;
    u[4] *= inv * g1.x; u[5] *= inv * g1.y; u[6] *= inv * g1.z; u[7] *= inv * g1.w;

    uint4 outw;
    uint32_t* ow = (uint32_t*)&outw;
#pragma unroll
    for (int j = 0; j < 4; ++j) {
        int pidx = tid * 4 + j;
        int i = pidx & 63;
        float sn, cs;
        sincosf(freqs[(size_t)s * 64 + i], &sn, &cs);
        float re = u[2 * j], im = u[2 * j + 1];
        __half2 hv = __floats2half2_rn(re * cs - im * sn, re * sn + im * cs);
        ow[j] = *(uint32_t*)&hv;
    }
    *(uint4*)(p + tid * 8) = outw;
}

// ---------------------------------------------------------------------------
// Flash attention fp16, register-double-buffered fragments.
// smem: K [0,49152) 3 stages, V [49152,98304), P [98304,114688).
// ---------------------------------------------------------------------------
#define FA_SMEM_BYTES 114688

__global__ __launch_bounds__(256) void flash_f16(
    const __half* __restrict__ QKV, const int* __restrict__ seq_lens,
    __half* __restrict__ Og)
{
    extern __shared__ char smf[];
    const uint32_t sb = (uint32_t)__cvta_generic_to_shared(smf);
    const int tid = threadIdx.x, lane = tid & 31, w = tid >> 5;
    const int g = lane >> 2, tig = lane & 3;
    const int bh = blockIdx.y, b = bh >> 4, h = bh & 15;
    const int q0 = blockIdx.x * 128;
    const int len = seq_lens[b];
    const float scale = 0.088388347648318447f;  // 1/sqrt(128)

    const __half* Qb = QKV + (size_t)b * S * N_QKV + h * HD;
    const __half* Kb = Qb + D;
    const __half* Vb = Qb + 2 * D;

    const int tl = lane >> 3, lr = lane & 7;
    const int rowoff = ((tl & 1) << 3) + lr;
    const int kadd = tl >> 1;
    const int fro = tid >> 4, fc16 = tid & 15;

#define KV_FILL(st, j0)                                                         \
    do {                                                                        \
        _Pragma("unroll")                                                       \
        for (int i = 0; i < 4; ++i) {                                           \
            int row = fro + 16 * i;                                             \
            uint32_t soff = (uint32_t)(row * 256 + ((fc16 ^ (row & 7)) << 4));  \
            cpa16(sb + (st) * 16384 + soff,                                     \
                  Kb + (size_t)((j0) + row) * N_QKV + fc16 * 8);                \
            cpa16(sb + 49152 + (st) * 16384 + soff,                             \
                  Vb + (size_t)((j0) + row) * N_QKV + fc16 * 8);                \
        }                                                                       \
    } while (0)

    KV_FILL(0, 0);  CP_COMMIT;
    KV_FILL(1, 64); CP_COMMIT;

    // Q fragments direct from gmem (rows w*16+g, w*16+g+8)
    uint32_t qf[8][4];
    {
        const __half* r0p = Qb + (size_t)(q0 + w * 16 + g) * N_QKV;
        const __half* r1p = r0p + (size_t)8 * N_QKV;
#pragma unroll
        for (int ks = 0; ks < 8; ++ks) {
            int c = ks * 16 + 2 * tig;
            qf[ks][0] = *(const uint32_t*)(r0p + c);
            qf[ks][1] = *(const uint32_t*)(r1p + c);
            qf[ks][2] = *(const uint32_t*)(r0p + c + 8);
            qf[ks][3] = *(const uint32_t*)(r1p + c + 8);
        }
    }

    float o[16][4];
#pragma unroll
    for (int nt = 0; nt < 16; ++nt)
#pragma unroll
        for (int e = 0; e < 4; ++e) o[nt][e] = 0.f;
    float m0 = -1e30f, m1 = -1e30f, l0 = 0.f, l1 = 0.f;

    const uint32_t pbase = sb + 98304;
    const int prA = w * 16 + g, prB = prA + 8;
    const uint32_t paddrA = pbase + prA * 128;
    const uint32_t paddrB = pbase + prB * 128;

    for (int t = 0; t < 32; ++t) {
        CP_WAIT(1);
        __syncthreads();
        if (t + 2 < 32) KV_FILL((t + 2) % 3, (t + 2) * 64);
        CP_COMMIT;
        const int st = t % 3;
        const uint32_t kst = sb + st * 16384;
        const uint32_t vst = sb + 49152 + st * 16384;

        // ---- S = Q @ K^T, kb double-buffered ----
        float s[8][4];
#pragma unroll
        for (int nt = 0; nt < 8; ++nt)
#pragma unroll
            for (int e = 0; e < 4; ++e) s[nt][e] = 0.f;

        uint32_t kb[2][4][4];
#define LD_KB(buf, ks)                                                          \
        do {                                                                    \
            const int c16 = 2 * (ks) + kadd;                                    \
            _Pragma("unroll")                                                   \
            for (int np = 0; np < 4; ++np) {                                    \
                int row = np * 16 + rowoff;                                     \
                ldm_x4(kb[buf][np], kst + row * 256 + ((c16 ^ (row & 7)) << 4));\
            }                                                                   \
        } while (0)

        LD_KB(0, 0);
#pragma unroll
        for (int ks = 0; ks < 8; ++ks) {
            const int kc = ks & 1;
            if (ks < 7) LD_KB(kc ^ 1, ks + 1);
#pragma unroll
            for (int np = 0; np < 4; ++np) {
                mma_f16(s[2 * np],     qf[ks], kb[kc][np][0], kb[kc][np][2]);
                mma_f16(s[2 * np + 1], qf[ks], kb[kc][np][1], kb[kc][np][3]);
            }
        }
#undef LD_KB

        const int j0 = t * 64;
        if (j0 + 64 > len) {
#pragma unroll
            for (int nt = 0; nt < 8; ++nt) {
                int c = j0 + nt * 8 + 2 * tig;
                if (c     >= len) { s[nt][0] = -1e30f; s[nt][2] = -1e30f; }
                if (c + 1 >= len) { s[nt][1] = -1e30f; s[nt][3] = -1e30f; }
            }
        }

        // ---- online softmax (rows g, g+8) ----
        float mx0 = -1e30f, mx1 = -1e30f;
#pragma unroll
        for (int nt = 0; nt < 8; ++nt) {
            mx0 = fmaxf(mx0, fmaxf(s[nt][0], s[nt][1]));
            mx1 = fmaxf(mx1, fmaxf(s[nt][2], s[nt][3]));
        }
        mx0 = fmaxf(mx0, __shfl_xor_sync(0xffffffffu, mx0, 1));
        mx0 = fmaxf(mx0, __shfl_xor_sync(0xffffffffu, mx0, 2));
        mx1 = fmaxf(mx1, __shfl_xor_sync(0xffffffffu, mx1, 1));
        mx1 = fmaxf(mx1, __shfl_xor_sync(0xffffffffu, mx1, 2));
        float mn0 = fmaxf(m0, mx0), mn1 = fmaxf(m1, mx1);
        float al0 = __expf(scale * (m0 - mn0));
        float al1 = __expf(scale * (m1 - mn1));
        float sum0 = 0.f, sum1 = 0.f;
#pragma unroll
        for (int nt = 0; nt < 8; ++nt) {
            s[nt][0] = __expf(scale * (s[nt][0] - mn0)); sum0 += s[nt][0];
            s[nt][1] = __expf(scale * (s[nt][1] - mn0)); sum0 += s[nt][1];
            s[nt][2] = __expf(scale * (s[nt][2] - mn1)); sum1 += s[nt][2];
            s[nt][3] = __expf(scale * (s[nt][3] - mn1)); sum1 += s[nt][3];
        }
        sum0 += __shfl_xor_sync(0xffffffffu, sum0, 1);
        sum0 += __shfl_xor_sync(0xffffffffu, sum0, 2);
        sum1 += __shfl_xor_sync(0xffffffffu, sum1, 1);
        sum1 += __shfl_xor_sync(0xffffffffu, sum1, 2);
        l0 = l0 * al0 + sum0; l1 = l1 * al1 + sum1;
        m0 = mn0; m1 = mn1;
#pragma unroll
        for (int nt = 0; nt < 16; ++nt) {
            o[nt][0] *= al0; o[nt][1] *= al0;
            o[nt][2] *= al1; o[nt][3] *= al1;
        }

        // ---- P -> per-warp smem (fp16) ----
#pragma unroll
        for (int nt = 0; nt < 8; ++nt) {
            __half2 hA = __floats2half2_rn(s[nt][0], s[nt][1]);
            __half2 hB = __floats2half2_rn(s[nt][2], s[nt][3]);
            uint32_t offA = ((nt ^ (prA & 7)) << 4) + 4 * tig;
            uint32_t offB = ((nt ^ (prB & 7)) << 4) + 4 * tig;
            *(uint32_t*)((char*)smf + (paddrA - sb) + offA) = *(uint32_t*)&hA;
            *(uint32_t*)((char*)smf + (paddrB - sb) + offB) = *(uint32_t*)&hB;
        }
        __syncwarp();

        // ---- O += P @ V, pa/vb double-buffered ----
        uint32_t pa[2][4], vb[2][4];
#define LD_PA(buf, ks)                                                          \
        do {                                                                    \
            int row = w * 16 + rowoff;                                          \
            int c16 = 2 * (ks) + kadd;                                          \
            ldm_x4(pa[buf], pbase + row * 128 + ((c16 ^ (row & 7)) << 4));      \
        } while (0)
#define LD_VB(buf, ks, np)                                                      \
        do {                                                                    \
            int row = (ks) * 16 + rowoff;                                       \
            int c16 = 2 * (np) + kadd;                                          \
            ldm_x4t(vb[buf], vst + row * 256 + ((c16 ^ (row & 7)) << 4));       \
        } while (0)

        LD_PA(0, 0);
        LD_VB(0, 0, 0);
#pragma unroll
        for (int ks = 0; ks < 4; ++ks) {
            const int pc = ks & 1;
            if (ks < 3) LD_PA(pc ^ 1, ks + 1);
#pragma unroll
            for (int np = 0; np < 8; ++np) {
                const int vc = np & 1;
                if (np < 7)       LD_VB(vc ^ 1, ks, np + 1);
                else if (ks < 3)  LD_VB(vc ^ 1, ks + 1, 0);
                mma_f16(o[2 * np],     pa[pc], vb[vc][0], vb[vc][1]);
                mma_f16(o[2 * np + 1], pa[pc], vb[vc][2], vb[vc][3]);
            }
        }
#undef LD_PA
#undef LD_VB
    }

    // ---- epilogue: normalize, store fp16 (row stride D) ----
    float li0 = 1.0f / l0, li1 = 1.0f / l1;
    __half* ObA = Og + (size_t)(b * S + q0 + w * 16 + g) * D + h * HD;
    __half* ObB = ObA + (size_t)8 * D;
#pragma unroll
    for (int nt = 0; nt < 16; ++nt) {
        int c = nt * 8 + 2 * tig;
        __half2 h0 = __floats2half2_rn(o[nt][0] * li0, o[nt][1] * li0);
        __half2 h1 = __floats2half2_rn(o[nt][2] * li1, o[nt][3] * li1);
        *(__half2*)(ObA + c) = h0;
        *(__half2*)(ObB + c) = h1;
    }
#undef KV_FILL
}

// ---------------------------------------------------------------------------
extern "C" void kernel_launch(void* const* d_in, const int* in_sizes, int n_in,
                              void* d_out, int out_size) {
    (void)in_sizes; (void)n_in; (void)out_size;
    const float* x        = (const float*)d_in[0];
    const int*   seq_lens = (const int*)  d_in[1];
    const float* freqs    = (const float*)d_in[2];
    const float* wq       = (const float*)d_in[3];
    const float* bq       = (const float*)d_in[4];
    const float* wk       = (const float*)d_in[5];
    const float* bk       = (const float*)d_in[6];
    const float* wv       = (const float*)d_in[7];
    const float* bv       = (const float*)d_in[8];
    const float* wo       = (const float*)d_in[9];
    const float* bo       = (const float*)d_in[10];
    const float* gq       = (const float*)d_in[11];
    const float* gk       = (const float*)d_in[12];
    float* out = (float*)d_out;

    __half *pxh, *pwh, *pqkv, *po;
    float* pbias;
    cudaGetSymbolAddress((void**)&pxh, g_xh);
    cudaGetSymbolAddress((void**)&pwh, g_wh);
    cudaGetSymbolAddress((void**)&pqkv, g_qkv);
    cudaGetSymbolAddress((void**)&po, g_oh);
    cudaGetSymbolAddress((void**)&pbias, g_bias);
    __half* pw3 = pwh + 3 * (size_t)D * D;      // wo

    cudaFuncSetAttribute(gemm_f16, cudaFuncAttributeMaxDynamicSharedMemorySize,
                         GEMM_SMEM_BYTES);
    cudaFuncSetAttribute(flash_f16, cudaFuncAttributeMaxDynamicSharedMemorySize,
                         FA_SMEM_BYTES);

    // launch 0: x conversion
    conv_h<<<(M_ROWS * D / 4 + 255) / 256, 256>>>(x, pxh, M_ROWS * D / 4);
    // launch 1: all weights + qkv bias
    conv_w4<<<(4 * (D * D / 4) + N_QKV + 255) / 256, 256>>>(
        wq, wk, wv, wo, bq, bk, bv, pwh, pbias);
    // launch 2: fused QKV projection (N = 6144, interleaved rows)
    gemm_f16<<<dim3(N_QKV / 256, M_ROWS / 128), 256, GEMM_SMEM_BYTES>>>(
        pxh, pwh, pbias, pqkv, nullptr, 0, N_QKV);
    // launch 3: Q and K rmsnorm+rope in one launch
    rmsnorm_rope_h<<<dim3(M_ROWS, 2), 256>>>(pqkv, gq, gk, freqs);
    // launch 4 (ncu capture slot): flash attention
    flash_f16<<<dim3(S / 128, B * NH), 256, FA_SMEM_BYTES>>>(
        pqkv, seq_lens, po);
    // launch 5: output projection
    gemm_f16<<<dim3(D / 256, M_ROWS / 128), 256, GEMM_SMEM_BYTES>>>(
        po, pw3, bo, nullptr, out, 1, D);
}

// round 9
// speedup vs baseline: 1.0441x; 1.0314x over previous
#include <cuda_runtime.h>
#include <cuda_fp16.h>
#include <math.h>
#include <stdint.h>

#define B 2
#define S 2048
#define D 2048
#define NH 16
#define HD 128
#define M_ROWS (B * S)
#define N_QKV (3 * D)

// Scratch (allocation-free rule: __device__ globals), fp16 operands
__device__ __half g_xh[(size_t)M_ROWS * D];
__device__ __half g_wh[4][(size_t)D * D];
__device__ __half g_qkv[(size_t)M_ROWS * N_QKV];   // interleaved Q|K|V per row
__device__ __half g_oh[(size_t)M_ROWS * D];
__device__ float  g_bias[N_QKV];
__device__ float2 g_trig[(size_t)S * 64];          // cos/sin per (s, pair)

// ---------------------------------------------------------------------------
// primitives
// ---------------------------------------------------------------------------
__device__ __forceinline__ void cpa16(uint32_t saddr, const void* gptr) {
    asm volatile("cp.async.cg.shared.global [%0], [%1], 16;\n"
                 :: "r"(saddr), "l"(gptr));
}
#define CP_COMMIT asm volatile("cp.async.commit_group;\n")
#define CP_WAIT(n) asm volatile("cp.async.wait_group %0;\n" :: "n"(n))

__device__ __forceinline__ void ldm_x4(uint32_t* r, uint32_t a) {
    asm volatile("ldmatrix.sync.aligned.m8n8.x4.shared.b16 {%0,%1,%2,%3}, [%4];"
                 : "=r"(r[0]), "=r"(r[1]), "=r"(r[2]), "=r"(r[3]) : "r"(a));
}
__device__ __forceinline__ void ldm_x4t(uint32_t* r, uint32_t a) {
    asm volatile("ldmatrix.sync.aligned.m8n8.x4.trans.shared.b16 {%0,%1,%2,%3}, [%4];"
                 : "=r"(r[0]), "=r"(r[1]), "=r"(r[2]), "=r"(r[3]) : "r"(a));
}
__device__ __forceinline__ void mma_f16(float* c, const uint32_t* a,
                                        uint32_t b0, uint32_t b1) {
    asm volatile(
        "mma.sync.aligned.m16n8k16.row.col.f32.f16.f16.f32 "
        "{%0,%1,%2,%3},{%4,%5,%6,%7},{%8,%9},{%0,%1,%2,%3};\n"
        : "+f"(c[0]), "+f"(c[1]), "+f"(c[2]), "+f"(c[3])
        : "r"(a[0]), "r"(a[1]), "r"(a[2]), "r"(a[3]), "r"(b0), "r"(b1));
}

// ---------------------------------------------------------------------------
// preamble kernels
// ---------------------------------------------------------------------------
__global__ void trig_k(const float* __restrict__ freqs, float2* __restrict__ trig) {
    int i = blockIdx.x * 256 + threadIdx.x;   // over S*64
    float sn, cs;
    sincosf(freqs[i], &sn, &cs);
    trig[i] = make_float2(cs, sn);
}

// grid-stride, 4x float4 per thread iteration
__global__ void conv_h(const float* __restrict__ src, __half* __restrict__ dst, int n4) {
    int stride = gridDim.x * 256;
    for (int i = blockIdx.x * 256 + threadIdx.x; i < n4; i += stride) {
        float4 v = ((const float4*)src)[i];
        __half2 h0 = __floats2half2_rn(v.x, v.y);
        __half2 h1 = __floats2half2_rn(v.z, v.w);
        ((uint2*)dst)[i] = make_uint2(*(uint32_t*)&h0, *(uint32_t*)&h1);
    }
}

// all 4 weights -> g_wh (grid-stride), plus qkv bias concat
__global__ void conv_w4(const float* __restrict__ w0, const float* __restrict__ w1,
                        const float* __restrict__ w2, const float* __restrict__ w3,
                        const float* __restrict__ bq, const float* __restrict__ bk,
                        const float* __restrict__ bv,
                        __half* __restrict__ dst, float* __restrict__ bias_dst) {
    const int per = D * D / 4;
    int stride = gridDim.x * 256;
    for (int i = blockIdx.x * 256 + threadIdx.x; i < 4 * per; i += stride) {
        int which = i / per, j = i - which * per;
        const float* src = (which == 0) ? w0 : (which == 1) ? w1
                         : (which == 2) ? w2 : w3;
        float4 v = ((const float4*)src)[j];
        __half2 h0 = __floats2half2_rn(v.x, v.y);
        __half2 h1 = __floats2half2_rn(v.z, v.w);
        ((uint2*)dst)[i] = make_uint2(*(uint32_t*)&h0, *(uint32_t*)&h1);
    }
    int j = blockIdx.x * 256 + threadIdx.x;
    if (j < N_QKV)
        bias_dst[j] = (j < D) ? bq[j] : (j < 2 * D) ? bk[j - D] : bv[j - 2 * D];
}

// ---------------------------------------------------------------------------
// fp16 GEMM, templated on warp-N frags WN: CTA tile 128 x (32*WN), 8 warps
// as 2(M) x 4(N) of 64 x (8*WN). BK=64, 4-stage cp.async, 1 sync/iter,
// register-double-buffered fragments.
// smem per stage: A 128 rows + B 32*WN rows, 128B each.
// ---------------------------------------------------------------------------
#define GEMM_SMEM_BYTES(WN) (4 * (128 + 32 * (WN)) * 128)

template <int WN>
__global__ __launch_bounds__(256) void gemm_f16(
    const __half* __restrict__ A, const __half* __restrict__ Wt,
    const float* __restrict__ bias, __half* __restrict__ Ch,
    float* __restrict__ Cf, int out_f32, int ldc)
{
    constexpr int TN = 32 * WN;            // CTA N tile
    constexpr int NB = WN / 2;             // B 16-row ldmatrix groups per warp
    constexpr int STG = (128 + TN) * 128;  // stage bytes
    extern __shared__ char smg[];
    const uint32_t sb = (uint32_t)__cvta_generic_to_shared(smg);
    const int tid = threadIdx.x, lane = tid & 31, w = tid >> 5;
    const int g = lane >> 2, tig = lane & 3;
    const int wm = w >> 2, wn = w & 3;
    const int bm = blockIdx.y * 128, bn = blockIdx.x * TN;

    const int tl = lane >> 3, lr = lane & 7;
    const int rowoff = ((tl & 1) << 3) + lr;
    const int kadd = tl >> 1;
    const int fro = tid >> 3, fc16 = tid & 7;

    float acc[4][WN][4];
#pragma unroll
    for (int mt = 0; mt < 4; ++mt)
#pragma unroll
        for (int nt = 0; nt < WN; ++nt)
#pragma unroll
            for (int e = 0; e < 4; ++e) acc[mt][nt][e] = 0.f;

#define GF(st, kt)                                                              \
    do {                                                                        \
        const int k0h = (kt) * 64;                                              \
        _Pragma("unroll")                                                       \
        for (int i = 0; i < 4; ++i) {                                           \
            int row = fro + 32 * i;                                             \
            cpa16(sb + (st) * STG + row * 128 + ((fc16 ^ (row & 7)) << 4),      \
                  A + (size_t)(bm + row) * D + k0h + fc16 * 8);                 \
        }                                                                       \
        _Pragma("unroll")                                                       \
        for (int i = 0; i < WN; ++i) {                                          \
            int row = fro + 32 * i;                                             \
            cpa16(sb + (st) * STG + 16384 + row * 128                           \
                      + ((fc16 ^ (row & 7)) << 4),                              \
                  Wt + (size_t)(bn + row) * D + k0h + fc16 * 8);                \
        }                                                                       \
    } while (0)

#define LD_FRAGS(buf, as, bs, ks)                                               \
    do {                                                                        \
        const int c16 = 2 * (ks) + kadd;                                        \
        _Pragma("unroll")                                                       \
        for (int mt = 0; mt < 4; ++mt) {                                        \
            int row = wm * 64 + mt * 16 + rowoff;                               \
            ldm_x4(af[buf][mt], (as) + row * 128 + ((c16 ^ (row & 7)) << 4));   \
        }                                                                       \
        _Pragma("unroll")                                                       \
        for (int np = 0; np < NB; ++np) {                                       \
            int row = wn * (8 * WN) + np * 16 + rowoff;                         \
            ldm_x4(bf[buf][np], (bs) + row * 128 + ((c16 ^ (row & 7)) << 4));   \
        }                                                                       \
    } while (0)

    GF(0, 0); CP_COMMIT;
    GF(1, 1); CP_COMMIT;
    GF(2, 2); CP_COMMIT;

    uint32_t af[2][4][4], bf[2][NB][4];

    for (int kt = 0; kt < 32; ++kt) {
        CP_WAIT(2);
        __syncthreads();
        if (kt + 3 < 32) { GF((kt + 3) & 3, kt + 3); }
        CP_COMMIT;
        const uint32_t as = sb + (kt & 3) * STG;
        const uint32_t bs = as + 16384;
        LD_FRAGS(0, as, bs, 0);
#pragma unroll
        for (int ks = 0; ks < 4; ++ks) {
            const int kc = ks & 1;
            if (ks < 3) LD_FRAGS(kc ^ 1, as, bs, ks + 1);
#pragma unroll
            for (int mt = 0; mt < 4; ++mt)
#pragma unroll
                for (int np = 0; np < NB; ++np) {
                    mma_f16(acc[mt][2 * np],     af[kc][mt], bf[kc][np][0], bf[kc][np][2]);
                    mma_f16(acc[mt][2 * np + 1], af[kc][mt], bf[kc][np][1], bf[kc][np][3]);
                }
        }
    }

    // epilogue
#pragma unroll
    for (int mt = 0; mt < 4; ++mt) {
        int r0 = bm + wm * 64 + mt * 16 + g;
#pragma unroll
        for (int nt = 0; nt < WN; ++nt) {
            int c = bn + wn * (8 * WN) + nt * 8 + 2 * tig;
            float b0 = bias[c], b1 = bias[c + 1];
            float v00 = acc[mt][nt][0] + b0, v01 = acc[mt][nt][1] + b1;
            float v10 = acc[mt][nt][2] + b0, v11 = acc[mt][nt][3] + b1;
            if (out_f32) {
                *(float2*)(Cf + (size_t)r0 * ldc + c) = make_float2(v00, v01);
                *(float2*)(Cf + (size_t)(r0 + 8) * ldc + c) = make_float2(v10, v11);
            } else {
                __half2 h0 = __floats2half2_rn(v00, v01);
                __half2 h1 = __floats2half2_rn(v10, v11);
                *(__half2*)(Ch + (size_t)r0 * ldc + c) = h0;
                *(__half2*)(Ch + (size_t)(r0 + 8) * ldc + c) = h1;
            }
        }
    }
#undef GF
#undef LD_FRAGS
}

// ---------------------------------------------------------------------------
// Fused RMSNorm+RoPE for BOTH Q and K (blockIdx.y selects), trig from table.
// ---------------------------------------------------------------------------
__global__ __launch_bounds__(256) void rmsnorm_rope_h(
    __half* __restrict__ qkv, const float* __restrict__ gq,
    const float* __restrict__ gk, const float2* __restrict__ trig)
{
    const int row = blockIdx.x;
    const int s = row & (S - 1);
    const int tid = threadIdx.x;
    const float* gw = blockIdx.y ? gk : gq;
    __half* p = qkv + (size_t)row * N_QKV + blockIdx.y * D;

    uint4 raw = *(const uint4*)(p + tid * 8);
    __half2 h[4] = { *(__half2*)&raw.x, *(__half2*)&raw.y,
                     *(__half2*)&raw.z, *(__half2*)&raw.w };
    float u[8];
#pragma unroll
    for (int j = 0; j < 4; ++j) {
        float2 f = __half22float2(h[j]);
        u[2 * j] = f.x; u[2 * j + 1] = f.y;
    }
    float ss = 0.f;
#pragma unroll
    for (int j = 0; j < 8; ++j) ss += u[j] * u[j];

    __shared__ float red[256];
    red[tid] = ss;
    __syncthreads();
    for (int off = 128; off > 0; off >>= 1) {
        if (tid < off) red[tid] += red[tid + off];
        __syncthreads();
    }
    const float inv = rsqrtf(red[0] / (float)D + 1e-6f);

    float4 g0 = *(const float4*)(gw + tid * 8);
    float4 g1 = *(const float4*)(gw + tid * 8 + 4);
    u[0] *= inv * g0.x; u[1] *= inv * g0.y; u[2] *= inv * g0.z; u[3] *= inv * g0.w;
    u[4] *= inv * g1.x; u[5] *= inv * g1.y; u[6] *= inv * g1.z; u[7] *= inv * g1.w;

    uint4 outw;
    uint32_t* ow = (uint32_t*)&outw;
#pragma unroll
    for (int j = 0; j < 4; ++j) {
        int pidx = tid * 4 + j;
        int i = pidx & 63;
        float2 cs = trig[(size_t)s * 64 + i];
        float re = u[2 * j], im = u[2 * j + 1];
        __half2 hv = __floats2half2_rn(re * cs.x - im * cs.y, re * cs.y + im * cs.x);
        ow[j] = *(uint32_t*)&hv;
    }
    *(uint4*)(p + tid * 8) = outw;
}

// ---------------------------------------------------------------------------
// Flash attention fp16, register-double-buffered fragments.
// smem: K [0,49152) 3 stages, V [49152,98304), P [98304,114688).
// ---------------------------------------------------------------------------
#define FA_SMEM_BYTES 114688

__global__ __launch_bounds__(256) void flash_f16(
    const __half* __restrict__ QKV, const int* __restrict__ seq_lens,
    __half* __restrict__ Og)
{
    extern __shared__ char smf[];
    const uint32_t sb = (uint32_t)__cvta_generic_to_shared(smf);
    const int tid = threadIdx.x, lane = tid & 31, w = tid >> 5;
    const int g = lane >> 2, tig = lane & 3;
    const int bh = blockIdx.y, b = bh >> 4, h = bh & 15;
    const int q0 = blockIdx.x * 128;
    const int len = seq_lens[b];
    const float scale = 0.088388347648318447f;  // 1/sqrt(128)

    const __half* Qb = QKV + (size_t)b * S * N_QKV + h * HD;
    const __half* Kb = Qb + D;
    const __half* Vb = Qb + 2 * D;

    const int tl = lane >> 3, lr = lane & 7;
    const int rowoff = ((tl & 1) << 3) + lr;
    const int kadd = tl >> 1;
    const int fro = tid >> 4, fc16 = tid & 15;

#define KV_FILL(st, j0)                                                         \
    do {                                                                        \
        _Pragma("unroll")                                                       \
        for (int i = 0; i < 4; ++i) {                                           \
            int row = fro + 16 * i;                                             \
            uint32_t soff = (uint32_t)(row * 256 + ((fc16 ^ (row & 7)) << 4));  \
            cpa16(sb + (st) * 16384 + soff,                                     \
                  Kb + (size_t)((j0) + row) * N_QKV + fc16 * 8);                \
            cpa16(sb + 49152 + (st) * 16384 + soff,                             \
                  Vb + (size_t)((j0) + row) * N_QKV + fc16 * 8);                \
        }                                                                       \
    } while (0)

    KV_FILL(0, 0);  CP_COMMIT;
    KV_FILL(1, 64); CP_COMMIT;

    // Q fragments direct from gmem (rows w*16+g, w*16+g+8)
    uint32_t qf[8][4];
    {
        const __half* r0p = Qb + (size_t)(q0 + w * 16 + g) * N_QKV;
        const __half* r1p = r0p + (size_t)8 * N_QKV;
#pragma unroll
        for (int ks = 0; ks < 8; ++ks) {
            int c = ks * 16 + 2 * tig;
            qf[ks][0] = *(const uint32_t*)(r0p + c);
            qf[ks][1] = *(const uint32_t*)(r1p + c);
            qf[ks][2] = *(const uint32_t*)(r0p + c + 8);
            qf[ks][3] = *(const uint32_t*)(r1p + c + 8);
        }
    }

    float o[16][4];
#pragma unroll
    for (int nt = 0; nt < 16; ++nt)
#pragma unroll
        for (int e = 0; e < 4; ++e) o[nt][e] = 0.f;
    float m0 = -1e30f, m1 = -1e30f, l0 = 0.f, l1 = 0.f;

    const uint32_t pbase = sb + 98304;
    const int prA = w * 16 + g, prB = prA + 8;
    const uint32_t paddrA = pbase + prA * 128;
    const uint32_t paddrB = pbase + prB * 128;

    for (int t = 0; t < 32; ++t) {
        CP_WAIT(1);
        __syncthreads();
        if (t + 2 < 32) KV_FILL((t + 2) % 3, (t + 2) * 64);
        CP_COMMIT;
        const int st = t % 3;
        const uint32_t kst = sb + st * 16384;
        const uint32_t vst = sb + 49152 + st * 16384;

        // ---- S = Q @ K^T, kb double-buffered ----
        float s[8][4];
#pragma unroll
        for (int nt = 0; nt < 8; ++nt)
#pragma unroll
            for (int e = 0; e < 4; ++e) s[nt][e] = 0.f;

        uint32_t kb[2][4][4];
#define LD_KB(buf, ks)                                                          \
        do {                                                                    \
            const int c16 = 2 * (ks) + kadd;                                    \
            _Pragma("unroll")                                                   \
            for (int np = 0; np < 4; ++np) {                                    \
                int row = np * 16 + rowoff;                                     \
                ldm_x4(kb[buf][np], kst + row * 256 + ((c16 ^ (row & 7)) << 4));\
            }                                                                   \
        } while (0)

        LD_KB(0, 0);
#pragma unroll
        for (int ks = 0; ks < 8; ++ks) {
            const int kc = ks & 1;
            if (ks < 7) LD_KB(kc ^ 1, ks + 1);
#pragma unroll
            for (int np = 0; np < 4; ++np) {
                mma_f16(s[2 * np],     qf[ks], kb[kc][np][0], kb[kc][np][2]);
                mma_f16(s[2 * np + 1], qf[ks], kb[kc][np][1], kb[kc][np][3]);
            }
        }
#undef LD_KB

        const int j0 = t * 64;
        if (j0 + 64 > len) {
#pragma unroll
            for (int nt = 0; nt < 8; ++nt) {
                int c = j0 + nt * 8 + 2 * tig;
                if (c     >= len) { s[nt][0] = -1e30f; s[nt][2] = -1e30f; }
                if (c + 1 >= len) { s[nt][1] = -1e30f; s[nt][3] = -1e30f; }
            }
        }

        // ---- online softmax (rows g, g+8) ----
        float mx0 = -1e30f, mx1 = -1e30f;
#pragma unroll
        for (int nt = 0; nt < 8; ++nt) {
            mx0 = fmaxf(mx0, fmaxf(s[nt][0], s[nt][1]));
            mx1 = fmaxf(mx1, fmaxf(s[nt][2], s[nt][3]));
        }
        mx0 = fmaxf(mx0, __shfl_xor_sync(0xffffffffu, mx0, 1));
        mx0 = fmaxf(mx0, __shfl_xor_sync(0xffffffffu, mx0, 2));
        mx1 = fmaxf(mx1, __shfl_xor_sync(0xffffffffu, mx1, 1));
        mx1 = fmaxf(mx1, __shfl_xor_sync(0xffffffffu, mx1, 2));
        float mn0 = fmaxf(m0, mx0), mn1 = fmaxf(m1, mx1);
        float al0 = __expf(scale * (m0 - mn0));
        float al1 = __expf(scale * (m1 - mn1));
        float sum0 = 0.f, sum1 = 0.f;
#pragma unroll
        for (int nt = 0; nt < 8; ++nt) {
            s[nt][0] = __expf(scale * (s[nt][0] - mn0)); sum0 += s[nt][0];
            s[nt][1] = __expf(scale * (s[nt][1] - mn0)); sum0 += s[nt][1];
            s[nt][2] = __expf(scale * (s[nt][2] - mn1)); sum1 += s[nt][2];
            s[nt][3] = __expf(scale * (s[nt][3] - mn1)); sum1 += s[nt][3];
        }
        sum0 += __shfl_xor_sync(0xffffffffu, sum0, 1);
        sum0 += __shfl_xor_sync(0xffffffffu, sum0, 2);
        sum1 += __shfl_xor_sync(0xffffffffu, sum1, 1);
        sum1 += __shfl_xor_sync(0xffffffffu, sum1, 2);
        l0 = l0 * al0 + sum0; l1 = l1 * al1 + sum1;
        m0 = mn0; m1 = mn1;
#pragma unroll
        for (int nt = 0; nt < 16; ++nt) {
            o[nt][0] *= al0; o[nt][1] *= al0;
            o[nt][2] *= al1; o[nt][3] *= al1;
        }

        // ---- P -> per-warp smem (fp16) ----
#pragma unroll
        for (int nt = 0; nt < 8; ++nt) {
            __half2 hA = __floats2half2_rn(s[nt][0], s[nt][1]);
            __half2 hB = __floats2half2_rn(s[nt][2], s[nt][3]);
            uint32_t offA = ((nt ^ (prA & 7)) << 4) + 4 * tig;
            uint32_t offB = ((nt ^ (prB & 7)) << 4) + 4 * tig;
            *(uint32_t*)((char*)smf + (paddrA - sb) + offA) = *(uint32_t*)&hA;
            *(uint32_t*)((char*)smf + (paddrB - sb) + offB) = *(uint32_t*)&hB;
        }
        __syncwarp();

        // ---- O += P @ V, pa/vb double-buffered ----
        uint32_t pa[2][4], vb[2][4];
#define LD_PA(buf, ks)                                                          \
        do {                                                                    \
            int row = w * 16 + rowoff;                                          \
            int c16 = 2 * (ks) + kadd;                                          \
            ldm_x4(pa[buf], pbase + row * 128 + ((c16 ^ (row & 7)) << 4));      \
        } while (0)
#define LD_VB(buf, ks, np)                                                      \
        do {                                                                    \
            int row = (ks) * 16 + rowoff;                                       \
            int c16 = 2 * (np) + kadd;                                          \
            ldm_x4t(vb[buf], vst + row * 256 + ((c16 ^ (row & 7)) << 4));       \
        } while (0)

        LD_PA(0, 0);
        LD_VB(0, 0, 0);
#pragma unroll
        for (int ks = 0; ks < 4; ++ks) {
            const int pc = ks & 1;
            if (ks < 3) LD_PA(pc ^ 1, ks + 1);
#pragma unroll
            for (int np = 0; np < 8; ++np) {
                const int vc = np & 1;
                if (np < 7)       LD_VB(vc ^ 1, ks, np + 1);
                else if (ks < 3)  LD_VB(vc ^ 1, ks + 1, 0);
                mma_f16(o[2 * np],     pa[pc], vb[vc][0], vb[vc][1]);
                mma_f16(o[2 * np + 1], pa[pc], vb[vc][2], vb[vc][3]);
            }
        }
#undef LD_PA
#undef LD_VB
    }

    // ---- epilogue: normalize, store fp16 (row stride D) ----
    float li0 = 1.0f / l0, li1 = 1.0f / l1;
    __half* ObA = Og + (size_t)(b * S + q0 + w * 16 + g) * D + h * HD;
    __half* ObB = ObA + (size_t)8 * D;
#pragma unroll
    for (int nt = 0; nt < 16; ++nt) {
        int c = nt * 8 + 2 * tig;
        __half2 h0 = __floats2half2_rn(o[nt][0] * li0, o[nt][1] * li0);
        __half2 h1 = __floats2half2_rn(o[nt][2] * li1, o[nt][3] * li1);
        *(__half2*)(ObA + c) = h0;
        *(__half2*)(ObB + c) = h1;
    }
#undef KV_FILL
}

// ---------------------------------------------------------------------------
extern "C" void kernel_launch(void* const* d_in, const int* in_sizes, int n_in,
                              void* d_out, int out_size) {
    (void)in_sizes; (void)n_in; (void)out_size;
    const float* x        = (const float*)d_in[0];
    const int*   seq_lens = (const int*)  d_in[1];
    const float* freqs    = (const float*)d_in[2];
    const float* wq       = (const float*)d_in[3];
    const float* bq       = (const float*)d_in[4];
    const float* wk       = (const float*)d_in[5];
    const float* bk       = (const float*)d_in[6];
    const float* wv       = (const float*)d_in[7];
    const float* bv       = (const float*)d_in[8];
    const float* wo       = (const float*)d_in[9];
    const float* bo       = (const float*)d_in[10];
    const float* gq       = (const float*)d_in[11];
    const float* gk       = (const float*)d_in[12];
    float* out = (float*)d_out;

    __half *pxh, *pwh, *pqkv, *po;
    float* pbias;
    float2* ptrig;
    cudaGetSymbolAddress((void**)&pxh, g_xh);
    cudaGetSymbolAddress((void**)&pwh, g_wh);
    cudaGetSymbolAddress((void**)&pqkv, g_qkv);
    cudaGetSymbolAddress((void**)&po, g_oh);
    cudaGetSymbolAddress((void**)&pbias, g_bias);
    cudaGetSymbolAddress((void**)&ptrig, g_trig);
    __half* pw3 = pwh + 3 * (size_t)D * D;      // wo

    cudaFuncSetAttribute(gemm_f16<6>, cudaFuncAttributeMaxDynamicSharedMemorySize,
                         GEMM_SMEM_BYTES(6));
    cudaFuncSetAttribute(gemm_f16<8>, cudaFuncAttributeMaxDynamicSharedMemorySize,
                         GEMM_SMEM_BYTES(8));
    cudaFuncSetAttribute(flash_f16, cudaFuncAttributeMaxDynamicSharedMemorySize,
                         FA_SMEM_BYTES);

    // preamble
    trig_k<<<S * 64 / 256, 256>>>(freqs, ptrig);
    conv_h<<<592, 256>>>(x, pxh, M_ROWS * D / 4);
    conv_w4<<<592, 256>>>(wq, wk, wv, wo, bq, bk, bv, pwh, pbias);
    // fused QKV projection: tile 128x192 -> 1024 CTAs (wave-tail friendly)
    gemm_f16<6><<<dim3(N_QKV / 192, M_ROWS / 128), 256, GEMM_SMEM_BYTES(6)>>>(
        pxh, pwh, pbias, pqkv, nullptr, 0, N_QKV);
    // Q and K rmsnorm+rope
    rmsnorm_rope_h<<<dim3(M_ROWS, 2), 256>>>(pqkv, gq, gk, ptrig);
    // flash attention
    flash_f16<<<dim3(S / 128, B * NH), 256, FA_SMEM_BYTES>>>(
        pqkv, seq_lens, po);
    // output projection: tile 128x256
    gemm_f16<8><<<dim3(D / 256, M_ROWS / 128), 256, GEMM_SMEM_BYTES(8)>>>(
        po, pw3, bo, nullptr, out, 1, D);
}

// round 10
// speedup vs baseline: 1.0783x; 1.0328x over previous
#include <cuda_runtime.h>
#include <cuda_fp16.h>
#include <math.h>
#include <stdint.h>

#define B 2
#define S 2048
#define D 2048
#define NH 16
#define HD 128
#define M_ROWS (B * S)
#define N_QKV (3 * D)

// Scratch (allocation-free rule: __device__ globals), fp16 operands
__device__ __half g_xh[(size_t)M_ROWS * D];
__device__ __half g_wh[4][(size_t)D * D];
__device__ __half g_qkv[(size_t)M_ROWS * N_QKV];   // interleaved Q|K|V per row
__device__ __half g_oh[(size_t)M_ROWS * D];
__device__ float  g_bias[N_QKV];
__device__ float2 g_trig[(size_t)S * 64];          // cos/sin per (s, pair)

// ---------------------------------------------------------------------------
// primitives
// ---------------------------------------------------------------------------
__device__ __forceinline__ void cpa16(uint32_t saddr, const void* gptr) {
    asm volatile("cp.async.cg.shared.global [%0], [%1], 16;\n"
                 :: "r"(saddr), "l"(gptr));
}
#define CP_COMMIT asm volatile("cp.async.commit_group;\n")
#define CP_WAIT(n) asm volatile("cp.async.wait_group %0;\n" :: "n"(n))

__device__ __forceinline__ void ldm_x4(uint32_t* r, uint32_t a) {
    asm volatile("ldmatrix.sync.aligned.m8n8.x4.shared.b16 {%0,%1,%2,%3}, [%4];"
                 : "=r"(r[0]), "=r"(r[1]), "=r"(r[2]), "=r"(r[3]) : "r"(a));
}
__device__ __forceinline__ void ldm_x4t(uint32_t* r, uint32_t a) {
    asm volatile("ldmatrix.sync.aligned.m8n8.x4.trans.shared.b16 {%0,%1,%2,%3}, [%4];"
                 : "=r"(r[0]), "=r"(r[1]), "=r"(r[2]), "=r"(r[3]) : "r"(a));
}
__device__ __forceinline__ void mma_f16(float* c, const uint32_t* a,
                                        uint32_t b0, uint32_t b1) {
    asm volatile(
        "mma.sync.aligned.m16n8k16.row.col.f32.f16.f16.f32 "
        "{%0,%1,%2,%3},{%4,%5,%6,%7},{%8,%9},{%0,%1,%2,%3};\n"
        : "+f"(c[0]), "+f"(c[1]), "+f"(c[2]), "+f"(c[3])
        : "r"(a[0]), "r"(a[1]), "r"(a[2]), "r"(a[3]), "r"(b0), "r"(b1));
}

// ---------------------------------------------------------------------------
// preamble kernels
// ---------------------------------------------------------------------------
__global__ void trig_k(const float* __restrict__ freqs, float2* __restrict__ trig) {
    int i = blockIdx.x * 256 + threadIdx.x;   // over S*64
    float sn, cs;
    sincosf(freqs[i], &sn, &cs);
    trig[i] = make_float2(cs, sn);
}

__global__ void conv_h(const float* __restrict__ src, __half* __restrict__ dst, int n4) {
    int stride = gridDim.x * 256;
    for (int i = blockIdx.x * 256 + threadIdx.x; i < n4; i += stride) {
        float4 v = ((const float4*)src)[i];
        __half2 h0 = __floats2half2_rn(v.x, v.y);
        __half2 h1 = __floats2half2_rn(v.z, v.w);
        ((uint2*)dst)[i] = make_uint2(*(uint32_t*)&h0, *(uint32_t*)&h1);
    }
}

__global__ void conv_w4(const float* __restrict__ w0, const float* __restrict__ w1,
                        const float* __restrict__ w2, const float* __restrict__ w3,
                        const float* __restrict__ bq, const float* __restrict__ bk,
                        const float* __restrict__ bv,
                        __half* __restrict__ dst, float* __restrict__ bias_dst) {
    const int per = D * D / 4;
    int stride = gridDim.x * 256;
    for (int i = blockIdx.x * 256 + threadIdx.x; i < 4 * per; i += stride) {
        int which = i / per, j = i - which * per;
        const float* src = (which == 0) ? w0 : (which == 1) ? w1
                         : (which == 2) ? w2 : w3;
        float4 v = ((const float4*)src)[j];
        __half2 h0 = __floats2half2_rn(v.x, v.y);
        __half2 h1 = __floats2half2_rn(v.z, v.w);
        ((uint2*)dst)[i] = make_uint2(*(uint32_t*)&h0, *(uint32_t*)&h1);
    }
    int j = blockIdx.x * 256 + threadIdx.x;
    if (j < N_QKV)
        bias_dst[j] = (j < D) ? bq[j] : (j < 2 * D) ? bk[j - D] : bv[j - 2 * D];
}

// ---------------------------------------------------------------------------
// fp16 GEMM, templated on warp-N frags WN, stage count NS, fill-ahead AH.
// CTA tile 128 x (32*WN), 8 warps as 2(M) x 4(N). BK=64 halves.
// Even-iteration-only barrier scheme: with NS >= AH+2, the stage filled at
// iter j was last consumed at j-2, so a barrier at even j (all warps past
// j-1) covers both fills; CP_WAIT(AH-2) at even j completes groups for
// stages j AND j+1 in every thread BEFORE the barrier, so odd iters need
// no wait/barrier.
// ---------------------------------------------------------------------------
#define GEMM_SMEM_BYTES(WN, NS) ((NS) * (128 + 32 * (WN)) * 128)

template <int WN, int NS, int AH>
__global__ __launch_bounds__(256) void gemm_f16(
    const __half* __restrict__ A, const __half* __restrict__ Wt,
    const float* __restrict__ bias, __half* __restrict__ Ch,
    float* __restrict__ Cf, int out_f32, int ldc)
{
    constexpr int TN = 32 * WN;
    constexpr int NB = WN / 2;
    constexpr int STG = (128 + TN) * 128;
    extern __shared__ char smg[];
    const uint32_t sb = (uint32_t)__cvta_generic_to_shared(smg);
    const int tid = threadIdx.x, lane = tid & 31, w = tid >> 5;
    const int g = lane >> 2, tig = lane & 3;
    const int wm = w >> 2, wn = w & 3;
    const int bm = blockIdx.y * 128, bn = blockIdx.x * TN;

    const int tl = lane >> 3, lr = lane & 7;
    const int rowoff = ((tl & 1) << 3) + lr;
    const int kadd = tl >> 1;
    const int fro = tid >> 3, fc16 = tid & 7;

    float acc[4][WN][4];
#pragma unroll
    for (int mt = 0; mt < 4; ++mt)
#pragma unroll
        for (int nt = 0; nt < WN; ++nt)
#pragma unroll
            for (int e = 0; e < 4; ++e) acc[mt][nt][e] = 0.f;

#define GF(st, kt)                                                              \
    do {                                                                        \
        const int k0h = (kt) * 64;                                              \
        _Pragma("unroll")                                                       \
        for (int i = 0; i < 4; ++i) {                                           \
            int row = fro + 32 * i;                                             \
            cpa16(sb + (st) * STG + row * 128 + ((fc16 ^ (row & 7)) << 4),      \
                  A + (size_t)(bm + row) * D + k0h + fc16 * 8);                 \
        }                                                                       \
        _Pragma("unroll")                                                       \
        for (int i = 0; i < WN; ++i) {                                          \
            int row = fro + 32 * i;                                             \
            cpa16(sb + (st) * STG + 16384 + row * 128                           \
                      + ((fc16 ^ (row & 7)) << 4),                              \
                  Wt + (size_t)(bn + row) * D + k0h + fc16 * 8);                \
        }                                                                       \
    } while (0)

#define LD_FRAGS(buf, as, bs, ks)                                               \
    do {                                                                        \
        const int c16 = 2 * (ks) + kadd;                                        \
        _Pragma("unroll")                                                       \
        for (int mt = 0; mt < 4; ++mt) {                                        \
            int row = wm * 64 + mt * 16 + rowoff;                               \
            ldm_x4(af[buf][mt], (as) + row * 128 + ((c16 ^ (row & 7)) << 4));   \
        }                                                                       \
        _Pragma("unroll")                                                       \
        for (int np = 0; np < NB; ++np) {                                       \
            int row = wn * (8 * WN) + np * 16 + rowoff;                         \
            ldm_x4(bf[buf][np], (bs) + row * 128 + ((c16 ^ (row & 7)) << 4));   \
        }                                                                       \
    } while (0)

#pragma unroll
    for (int p = 0; p < AH; ++p) { GF(p, p); CP_COMMIT; }

    uint32_t af[2][4][4], bf[2][NB][4];

    for (int kt = 0; kt < 32; ++kt) {
        if ((kt & 1) == 0) {
            CP_WAIT(AH - 2);
            __syncthreads();
        }
        const uint32_t as = sb + (kt % NS) * STG;
        const uint32_t bs = as + 16384;
        LD_FRAGS(0, as, bs, 0);          // LDSM latency hides under fill issue
        if (kt + AH < 32) { GF((kt + AH) % NS, kt + AH); }
        CP_COMMIT;
#pragma unroll
        for (int ks = 0; ks < 4; ++ks) {
            const int kc = ks & 1;
            if (ks < 3) LD_FRAGS(kc ^ 1, as, bs, ks + 1);
#pragma unroll
            for (int mt = 0; mt < 4; ++mt)
#pragma unroll
                for (int np = 0; np < NB; ++np) {
                    mma_f16(acc[mt][2 * np],     af[kc][mt], bf[kc][np][0], bf[kc][np][2]);
                    mma_f16(acc[mt][2 * np + 1], af[kc][mt], bf[kc][np][1], bf[kc][np][3]);
                }
        }
    }

    // epilogue
#pragma unroll
    for (int mt = 0; mt < 4; ++mt) {
        int r0 = bm + wm * 64 + mt * 16 + g;
#pragma unroll
        for (int nt = 0; nt < WN; ++nt) {
            int c = bn + wn * (8 * WN) + nt * 8 + 2 * tig;
            float b0 = bias[c], b1 = bias[c + 1];
            float v00 = acc[mt][nt][0] + b0, v01 = acc[mt][nt][1] + b1;
            float v10 = acc[mt][nt][2] + b0, v11 = acc[mt][nt][3] + b1;
            if (out_f32) {
                *(float2*)(Cf + (size_t)r0 * ldc + c) = make_float2(v00, v01);
                *(float2*)(Cf + (size_t)(r0 + 8) * ldc + c) = make_float2(v10, v11);
            } else {
                __half2 h0 = __floats2half2_rn(v00, v01);
                __half2 h1 = __floats2half2_rn(v10, v11);
                *(__half2*)(Ch + (size_t)r0 * ldc + c) = h0;
                *(__half2*)(Ch + (size_t)(r0 + 8) * ldc + c) = h1;
            }
        }
    }
#undef GF
#undef LD_FRAGS
}

// ---------------------------------------------------------------------------
// Fused RMSNorm+RoPE for BOTH Q and K (blockIdx.y selects), trig from table.
// ---------------------------------------------------------------------------
__global__ __launch_bounds__(256) void rmsnorm_rope_h(
    __half* __restrict__ qkv, const float* __restrict__ gq,
    const float* __restrict__ gk, const float2* __restrict__ trig)
{
    const int row = blockIdx.x;
    const int s = row & (S - 1);
    const int tid = threadIdx.x;
    const float* gw = blockIdx.y ? gk : gq;
    __half* p = qkv + (size_t)row * N_QKV + blockIdx.y * D;

    uint4 raw = *(const uint4*)(p + tid * 8);
    __half2 h[4] = { *(__half2*)&raw.x, *(__half2*)&raw.y,
                     *(__half2*)&raw.z, *(__half2*)&raw.w };
    float u[8];
#pragma unroll
    for (int j = 0; j < 4; ++j) {
        float2 f = __half22float2(h[j]);
        u[2 * j] = f.x; u[2 * j + 1] = f.y;
    }
    float ss = 0.f;
#pragma unroll
    for (int j = 0; j < 8; ++j) ss += u[j] * u[j];

    __shared__ float red[256];
    red[tid] = ss;
    __syncthreads();
    for (int off = 128; off > 0; off >>= 1) {
        if (tid < off) red[tid] += red[tid + off];
        __syncthreads();
    }
    const float inv = rsqrtf(red[0] / (float)D + 1e-6f);

    float4 g0 = *(const float4*)(gw + tid * 8);
    float4 g1 = *(const float4*)(gw + tid * 8 + 4);
    u[0] *= inv * g0.x; u[1] *= inv * g0.y; u[2] *= inv * g0.z; u[3] *= inv * g0.w;
    u[4] *= inv * g1.x; u[5] *= inv * g1.y; u[6] *= inv * g1.z; u[7] *= inv * g1.w;

    uint4 outw;
    uint32_t* ow = (uint32_t*)&outw;
#pragma unroll
    for (int j = 0; j < 4; ++j) {
        int pidx = tid * 4 + j;
        int i = pidx & 63;
        float2 cs = trig[(size_t)s * 64 + i];
        float re = u[2 * j], im = u[2 * j + 1];
        __half2 hv = __floats2half2_rn(re * cs.x - im * cs.y, re * cs.y + im * cs.x);
        ow[j] = *(uint32_t*)&hv;
    }
    *(uint4*)(p + tid * 8) = outw;
}

// ---------------------------------------------------------------------------
// Flash attention fp16, 5-stage K/V pipeline with even-iteration barriers
// (same visibility scheme as the GEMM: AH=3, NS=5).
// smem: K 5 stages [0,81920), V 5 stages [81920,163840), P [163840,180224).
// ---------------------------------------------------------------------------
#define FA_SMEM_BYTES 180224

__global__ __launch_bounds__(256) void flash_f16(
    const __half* __restrict__ QKV, const int* __restrict__ seq_lens,
    __half* __restrict__ Og)
{
    extern __shared__ char smf[];
    const uint32_t sb = (uint32_t)__cvta_generic_to_shared(smf);
    const int tid = threadIdx.x, lane = tid & 31, w = tid >> 5;
    const int g = lane >> 2, tig = lane & 3;
    const int bh = blockIdx.y, b = bh >> 4, h = bh & 15;
    const int q0 = blockIdx.x * 128;
    const int len = seq_lens[b];
    const float scale = 0.088388347648318447f;  // 1/sqrt(128)

    const __half* Qb = QKV + (size_t)b * S * N_QKV + h * HD;
    const __half* Kb = Qb + D;
    const __half* Vb = Qb + 2 * D;

    const int tl = lane >> 3, lr = lane & 7;
    const int rowoff = ((tl & 1) << 3) + lr;
    const int kadd = tl >> 1;
    const int fro = tid >> 4, fc16 = tid & 15;

#define KV_FILL(st, j0)                                                         \
    do {                                                                        \
        _Pragma("unroll")                                                       \
        for (int i = 0; i < 4; ++i) {                                           \
            int row = fro + 16 * i;                                             \
            uint32_t soff = (uint32_t)(row * 256 + ((fc16 ^ (row & 7)) << 4));  \
            cpa16(sb + (st) * 16384 + soff,                                     \
                  Kb + (size_t)((j0) + row) * N_QKV + fc16 * 8);                \
            cpa16(sb + 81920 + (st) * 16384 + soff,                             \
                  Vb + (size_t)((j0) + row) * N_QKV + fc16 * 8);                \
        }                                                                       \
    } while (0)

    KV_FILL(0, 0);   CP_COMMIT;
    KV_FILL(1, 64);  CP_COMMIT;
    KV_FILL(2, 128); CP_COMMIT;

    // Q fragments direct from gmem (rows w*16+g, w*16+g+8)
    uint32_t qf[8][4];
    {
        const __half* r0p = Qb + (size_t)(q0 + w * 16 + g) * N_QKV;
        const __half* r1p = r0p + (size_t)8 * N_QKV;
#pragma unroll
        for (int ks = 0; ks < 8; ++ks) {
            int c = ks * 16 + 2 * tig;
            qf[ks][0] = *(const uint32_t*)(r0p + c);
            qf[ks][1] = *(const uint32_t*)(r1p + c);
            qf[ks][2] = *(const uint32_t*)(r0p + c + 8);
            qf[ks][3] = *(const uint32_t*)(r1p + c + 8);
        }
    }

    float o[16][4];
#pragma unroll
    for (int nt = 0; nt < 16; ++nt)
#pragma unroll
        for (int e = 0; e < 4; ++e) o[nt][e] = 0.f;
    float m0 = -1e30f, m1 = -1e30f, l0 = 0.f, l1 = 0.f;

    const uint32_t pbase = sb + 163840;
    const int prA = w * 16 + g, prB = prA + 8;
    const uint32_t paddrA = pbase + prA * 128;
    const uint32_t paddrB = pbase + prB * 128;

    for (int t = 0; t < 32; ++t) {
        if ((t & 1) == 0) {
            CP_WAIT(1);
            __syncthreads();
        }
        if (t + 3 < 32) KV_FILL((t + 3) % 5, (t + 3) * 64);
        CP_COMMIT;
        const int st = t % 5;
        const uint32_t kst = sb + st * 16384;
        const uint32_t vst = sb + 81920 + st * 16384;

        // ---- S = Q @ K^T, kb double-buffered ----
        float s[8][4];
#pragma unroll
        for (int nt = 0; nt < 8; ++nt)
#pragma unroll
            for (int e = 0; e < 4; ++e) s[nt][e] = 0.f;

        uint32_t kb[2][4][4];
#define LD_KB(buf, ks)                                                          \
        do {                                                                    \
            const int c16 = 2 * (ks) + kadd;                                    \
            _Pragma("unroll")                                                   \
            for (int np = 0; np < 4; ++np) {                                    \
                int row = np * 16 + rowoff;                                     \
                ldm_x4(kb[buf][np], kst + row * 256 + ((c16 ^ (row & 7)) << 4));\
            }                                                                   \
        } while (0)

        LD_KB(0, 0);
#pragma unroll
        for (int ks = 0; ks < 8; ++ks) {
            const int kc = ks & 1;
            if (ks < 7) LD_KB(kc ^ 1, ks + 1);
#pragma unroll
            for (int np = 0; np < 4; ++np) {
                mma_f16(s[2 * np],     qf[ks], kb[kc][np][0], kb[kc][np][2]);
                mma_f16(s[2 * np + 1], qf[ks], kb[kc][np][1], kb[kc][np][3]);
            }
        }
#undef LD_KB

        const int j0 = t * 64;
        if (j0 + 64 > len) {
#pragma unroll
            for (int nt = 0; nt < 8; ++nt) {
                int c = j0 + nt * 8 + 2 * tig;
                if (c     >= len) { s[nt][0] = -1e30f; s[nt][2] = -1e30f; }
                if (c + 1 >= len) { s[nt][1] = -1e30f; s[nt][3] = -1e30f; }
            }
        }

        // ---- online softmax (rows g, g+8) ----
        float mx0 = -1e30f, mx1 = -1e30f;
#pragma unroll
        for (int nt = 0; nt < 8; ++nt) {
            mx0 = fmaxf(mx0, fmaxf(s[nt][0], s[nt][1]));
            mx1 = fmaxf(mx1, fmaxf(s[nt][2], s[nt][3]));
        }
        mx0 = fmaxf(mx0, __shfl_xor_sync(0xffffffffu, mx0, 1));
        mx0 = fmaxf(mx0, __shfl_xor_sync(0xffffffffu, mx0, 2));
        mx1 = fmaxf(mx1, __shfl_xor_sync(0xffffffffu, mx1, 1));
        mx1 = fmaxf(mx1, __shfl_xor_sync(0xffffffffu, mx1, 2));
        float mn0 = fmaxf(m0, mx0), mn1 = fmaxf(m1, mx1);
        float al0 = __expf(scale * (m0 - mn0));
        float al1 = __expf(scale * (m1 - mn1));
        float sum0 = 0.f, sum1 = 0.f;
#pragma unroll
        for (int nt = 0; nt < 8; ++nt) {
            s[nt][0] = __expf(scale * (s[nt][0] - mn0)); sum0 += s[nt][0];
            s[nt][1] = __expf(scale * (s[nt][1] - mn0)); sum0 += s[nt][1];
            s[nt][2] = __expf(scale * (s[nt][2] - mn1)); sum1 += s[nt][2];
            s[nt][3] = __expf(scale * (s[nt][3] - mn1)); sum1 += s[nt][3];
        }
        sum0 += __shfl_xor_sync(0xffffffffu, sum0, 1);
        sum0 += __shfl_xor_sync(0xffffffffu, sum0, 2);
        sum1 += __shfl_xor_sync(0xffffffffu, sum1, 1);
        sum1 += __shfl_xor_sync(0xffffffffu, sum1, 2);
        l0 = l0 * al0 + sum0; l1 = l1 * al1 + sum1;
        m0 = mn0; m1 = mn1;
#pragma unroll
        for (int nt = 0; nt < 16; ++nt) {
            o[nt][0] *= al0; o[nt][1] *= al0;
            o[nt][2] *= al1; o[nt][3] *= al1;
        }

        // ---- P -> per-warp smem (fp16) ----
#pragma unroll
        for (int nt = 0; nt < 8; ++nt) {
            __half2 hA = __floats2half2_rn(s[nt][0], s[nt][1]);
            __half2 hB = __floats2half2_rn(s[nt][2], s[nt][3]);
            uint32_t offA = ((nt ^ (prA & 7)) << 4) + 4 * tig;
            uint32_t offB = ((nt ^ (prB & 7)) << 4) + 4 * tig;
            *(uint32_t*)((char*)smf + (paddrA - sb) + offA) = *(uint32_t*)&hA;
            *(uint32_t*)((char*)smf + (paddrB - sb) + offB) = *(uint32_t*)&hB;
        }
        __syncwarp();

        // ---- O += P @ V, pa/vb double-buffered ----
        uint32_t pa[2][4], vb[2][4];
#define LD_PA(buf, ks)                                                          \
        do {                                                                    \
            int row = w * 16 + rowoff;                                          \
            int c16 = 2 * (ks) + kadd;                                          \
            ldm_x4(pa[buf], pbase + row * 128 + ((c16 ^ (row & 7)) << 4));      \
        } while (0)
#define LD_VB(buf, ks, np)                                                      \
        do {                                                                    \
            int row = (ks) * 16 + rowoff;                                       \
            int c16 = 2 * (np) + kadd;                                          \
            ldm_x4t(vb[buf], vst + row * 256 + ((c16 ^ (row & 7)) << 4));       \
        } while (0)

        LD_PA(0, 0);
        LD_VB(0, 0, 0);
#pragma unroll
        for (int ks = 0; ks < 4; ++ks) {
            const int pc = ks & 1;
            if (ks < 3) LD_PA(pc ^ 1, ks + 1);
#pragma unroll
            for (int np = 0; np < 8; ++np) {
                const int vc = np & 1;
                if (np < 7)       LD_VB(vc ^ 1, ks, np + 1);
                else if (ks < 3)  LD_VB(vc ^ 1, ks + 1, 0);
                mma_f16(o[2 * np],     pa[pc], vb[vc][0], vb[vc][1]);
                mma_f16(o[2 * np + 1], pa[pc], vb[vc][2], vb[vc][3]);
            }
        }
#undef LD_PA
#undef LD_VB
    }

    // ---- epilogue: normalize, store fp16 (row stride D) ----
    float li0 = 1.0f / l0, li1 = 1.0f / l1;
    __half* ObA = Og + (size_t)(b * S + q0 + w * 16 + g) * D + h * HD;
    __half* ObB = ObA + (size_t)8 * D;
#pragma unroll
    for (int nt = 0; nt < 16; ++nt) {
        int c = nt * 8 + 2 * tig;
        __half2 h0 = __floats2half2_rn(o[nt][0] * li0, o[nt][1] * li0);
        __half2 h1 = __floats2half2_rn(o[nt][2] * li1, o[nt][3] * li1);
        *(__half2*)(ObA + c) = h0;
        *(__half2*)(ObB + c) = h1;
    }
#undef KV_FILL
}

// ---------------------------------------------------------------------------
extern "C" void kernel_launch(void* const* d_in, const int* in_sizes, int n_in,
                              void* d_out, int out_size) {
    (void)in_sizes; (void)n_in; (void)out_size;
    const float* x        = (const float*)d_in[0];
    const int*   seq_lens = (const int*)  d_in[1];
    const float* freqs    = (const float*)d_in[2];
    const float* wq       = (const float*)d_in[3];
    const float* bq       = (const float*)d_in[4];
    const float* wk       = (const float*)d_in[5];
    const float* bk       = (const float*)d_in[6];
    const float* wv       = (const float*)d_in[7];
    const float* bv       = (const float*)d_in[8];
    const float* wo       = (const float*)d_in[9];
    const float* bo       = (const float*)d_in[10];
    const float* gq       = (const float*)d_in[11];
    const float* gk       = (const float*)d_in[12];
    float* out = (float*)d_out;

    __half *pxh, *pwh, *pqkv, *po;
    float* pbias;
    float2* ptrig;
    cudaGetSymbolAddress((void**)&pxh, g_xh);
    cudaGetSymbolAddress((void**)&pwh, g_wh);
    cudaGetSymbolAddress((void**)&pqkv, g_qkv);
    cudaGetSymbolAddress((void**)&po, g_oh);
    cudaGetSymbolAddress((void**)&pbias, g_bias);
    cudaGetSymbolAddress((void**)&ptrig, g_trig);
    __half* pw3 = pwh + 3 * (size_t)D * D;      // wo

    cudaFuncSetAttribute(gemm_f16<6, 5, 3>,
                         cudaFuncAttributeMaxDynamicSharedMemorySize,
                         GEMM_SMEM_BYTES(6, 5));
    cudaFuncSetAttribute(gemm_f16<8, 4, 2>,
                         cudaFuncAttributeMaxDynamicSharedMemorySize,
                         GEMM_SMEM_BYTES(8, 4));
    cudaFuncSetAttribute(flash_f16, cudaFuncAttributeMaxDynamicSharedMemorySize,
                         FA_SMEM_BYTES);

    // preamble
    trig_k<<<S * 64 / 256, 256>>>(freqs, ptrig);
    conv_h<<<592, 256>>>(x, pxh, M_ROWS * D / 4);
    conv_w4<<<592, 256>>>(wq, wk, wv, wo, bq, bk, bv, pwh, pbias);
    // fused QKV projection: tile 128x192 -> 1024 CTAs, 5-stage pipeline
    gemm_f16<6, 5, 3><<<dim3(N_QKV / 192, M_ROWS / 128), 256,
                        GEMM_SMEM_BYTES(6, 5)>>>(
        pxh, pwh, pbias, pqkv, nullptr, 0, N_QKV);
    // Q and K rmsnorm+rope
    rmsnorm_rope_h<<<dim3(M_ROWS, 2), 256>>>(pqkv, gq, gk, ptrig);
    // flash attention
    flash_f16<<<dim3(S / 128, B * NH), 256, FA_SMEM_BYTES>>>(
        pqkv, seq_lens, po);
    // output projection: tile 128x256, 4-stage
    gemm_f16<8, 4, 2><<<dim3(D / 256, M_ROWS / 128), 256,
                        GEMM_SMEM_BYTES(8, 4)>>>(
        po, pw3, bo, nullptr, out, 1, D);
}

// round 13
// speedup vs baseline: 1.1035x; 1.0233x over previous
#include <cuda_runtime.h>
#include <cuda_fp16.h>
#include <math.h>
#include <stdint.h>

#define B 2
#define S 2048
#define D 2048
#define NH 16
#define HD 128
#define M_ROWS (B * S)
#define N_QKV (3 * D)

// Scratch (allocation-free rule: __device__ globals), fp16 operands
__device__ __half g_xh[(size_t)M_ROWS * D];
__device__ __half g_wh[4][(size_t)D * D];
__device__ __half g_qkv[(size_t)M_ROWS * N_QKV];   // interleaved Q|K|V per row
__device__ __half g_oh[(size_t)M_ROWS * D];
__device__ float  g_bias[N_QKV];
__device__ float2 g_trig[(size_t)S * 64];          // cos/sin per (s, pair)

// ---------------------------------------------------------------------------
// primitives
// ---------------------------------------------------------------------------
__device__ __forceinline__ void cpa16(uint32_t saddr, const void* gptr) {
    asm volatile("cp.async.cg.shared.global [%0], [%1], 16;\n"
                 :: "r"(saddr), "l"(gptr));
}
#define CP_COMMIT asm volatile("cp.async.commit_group;\n")
#define CP_WAIT(n) asm volatile("cp.async.wait_group %0;\n" :: "n"(n))

__device__ __forceinline__ void ldm_x4(uint32_t* r, uint32_t a) {
    asm volatile("ldmatrix.sync.aligned.m8n8.x4.shared.b16 {%0,%1,%2,%3}, [%4];"
                 : "=r"(r[0]), "=r"(r[1]), "=r"(r[2]), "=r"(r[3]) : "r"(a));
}
__device__ __forceinline__ void ldm_x4t(uint32_t* r, uint32_t a) {
    asm volatile("ldmatrix.sync.aligned.m8n8.x4.trans.shared.b16 {%0,%1,%2,%3}, [%4];"
                 : "=r"(r[0]), "=r"(r[1]), "=r"(r[2]), "=r"(r[3]) : "r"(a));
}
__device__ __forceinline__ void mma_f16(float* c, const uint32_t* a,
                                        uint32_t b0, uint32_t b1) {
    asm volatile(
        "mma.sync.aligned.m16n8k16.row.col.f32.f16.f16.f32 "
        "{%0,%1,%2,%3},{%4,%5,%6,%7},{%8,%9},{%0,%1,%2,%3};\n"
        : "+f"(c[0]), "+f"(c[1]), "+f"(c[2]), "+f"(c[3])
        : "r"(a[0]), "r"(a[1]), "r"(a[2]), "r"(a[3]), "r"(b0), "r"(b1));
}

// ---------------------------------------------------------------------------
// preamble kernels
// ---------------------------------------------------------------------------
__global__ void trig_k(const float* __restrict__ freqs, float2* __restrict__ trig) {
    int i = blockIdx.x * 256 + threadIdx.x;   // over S*64
    float sn, cs;
    sincosf(freqs[i], &sn, &cs);
    trig[i] = make_float2(cs, sn);
}

__global__ void conv_h(const float* __restrict__ src, __half* __restrict__ dst, int n4) {
    int stride = gridDim.x * 256;
    for (int i = blockIdx.x * 256 + threadIdx.x; i < n4; i += stride) {
        float4 v = ((const float4*)src)[i];
        __half2 h0 = __floats2half2_rn(v.x, v.y);
        __half2 h1 = __floats2half2_rn(v.z, v.w);
        ((uint2*)dst)[i] = make_uint2(*(uint32_t*)&h0, *(uint32_t*)&h1);
    }
}

__global__ void conv_w4(const float* __restrict__ w0, const float* __restrict__ w1,
                        const float* __restrict__ w2, const float* __restrict__ w3,
                        const float* __restrict__ bq, const float* __restrict__ bk,
                        const float* __restrict__ bv,
                        __half* __restrict__ dst, float* __restrict__ bias_dst) {
    const int per = D * D / 4;
    int stride = gridDim.x * 256;
    for (int i = blockIdx.x * 256 + threadIdx.x; i < 4 * per; i += stride) {
        int which = i / per, j = i - which * per;
        const float* src = (which == 0) ? w0 : (which == 1) ? w1
                         : (which == 2) ? w2 : w3;
        float4 v = ((const float4*)src)[j];
        __half2 h0 = __floats2half2_rn(v.x, v.y);
        __half2 h1 = __floats2half2_rn(v.z, v.w);
        ((uint2*)dst)[i] = make_uint2(*(uint32_t*)&h0, *(uint32_t*)&h1);
    }
    int j = blockIdx.x * 256 + threadIdx.x;
    if (j < N_QKV)
        bias_dst[j] = (j < D) ? bq[j] : (j < 2 * D) ? bk[j - D] : bv[j - 2 * D];
}

// ---------------------------------------------------------------------------
// fp16 GEMM, templated on warp-N frags WN, warps-in-N NWN, stages NS,
// fill-ahead AH. CTA tile 128 x (8*WN*NWN); 2*NWN warps (2 in M x NWN in N);
// warp tile 64 x (8*WN). BK=64 halves. Even-iteration-only barrier scheme
// (valid when NS >= AH+2; see R9 derivation).
// ---------------------------------------------------------------------------
#define GEMM_SMEM_B(WN, NWN, NS) ((NS) * (128 + 8 * (WN) * (NWN)) * 128)

template <int WN, int NWN, int NS, int AH>
__global__ __launch_bounds__(64 * NWN) void gemm_f16(
    const __half* __restrict__ A, const __half* __restrict__ Wt,
    const float* __restrict__ bias, __half* __restrict__ Ch,
    float* __restrict__ Cf, int out_f32, int ldc)
{
    constexpr int TN = 8 * WN * NWN;       // CTA N tile
    constexpr int NB = WN / 2;             // B 16-row ldmatrix groups per warp
    constexpr int NT = 64 * NWN;           // threads
    constexpr int STG = (128 + TN) * 128;  // stage bytes
    constexpr int TOT = (128 + TN) * 8;    // cp.async ops per stage
    constexpr int NI = (TOT + NT - 1) / NT;
    extern __shared__ char smg[];
    const uint32_t sb = (uint32_t)__cvta_generic_to_shared(smg);
    const int tid = threadIdx.x, lane = tid & 31, w = tid >> 5;
    const int g = lane >> 2, tig = lane & 3;
    const int wm = w / NWN, wn = w % NWN;
    const int bm = blockIdx.y * 128, bn = blockIdx.x * TN;

    const int tl = lane >> 3, lr = lane & 7;
    const int rowoff = ((tl & 1) << 3) + lr;
    const int kadd = tl >> 1;

    float acc[4][WN][4];
#pragma unroll
    for (int mt = 0; mt < 4; ++mt)
#pragma unroll
        for (int nt = 0; nt < WN; ++nt)
#pragma unroll
            for (int e = 0; e < 4; ++e) acc[mt][nt][e] = 0.f;

#define GF(st, kt)                                                              \
    do {                                                                        \
        const int k0h = (kt) * 64;                                              \
        _Pragma("unroll")                                                       \
        for (int i = 0; i < NI; ++i) {                                          \
            int id = tid + NT * i;                                              \
            if (TOT % NT == 0 || id < TOT) {                                    \
                int row = id >> 3, c16 = id & 7;                                \
                uint32_t soff = (uint32_t)(row * 128 + ((c16 ^ (row & 7)) << 4));\
                const __half* gp = (row < 128)                                  \
                    ? A  + (size_t)(bm + row) * D + k0h + c16 * 8               \
                    : Wt + (size_t)(bn + row - 128) * D + k0h + c16 * 8;        \
                cpa16(sb + (st) * STG + soff, gp);                              \
            }                                                                   \
        }                                                                       \
    } while (0)

#define LD_FRAGS(buf, as, bs, ks)                                               \
    do {                                                                        \
        const int c16 = 2 * (ks) + kadd;                                        \
        _Pragma("unroll")                                                       \
        for (int mt = 0; mt < 4; ++mt) {                                        \
            int row = wm * 64 + mt * 16 + rowoff;                               \
            ldm_x4(af[buf][mt], (as) + row * 128 + ((c16 ^ (row & 7)) << 4));   \
        }                                                                       \
        _Pragma("unroll")                                                       \
        for (int np = 0; np < NB; ++np) {                                       \
            int row = wn * (8 * WN) + np * 16 + rowoff;                         \
            ldm_x4(bf[buf][np], (bs) + row * 128 + ((c16 ^ (row & 7)) << 4));   \
        }                                                                       \
    } while (0)

#pragma unroll
    for (int p = 0; p < AH; ++p) { GF(p, p); CP_COMMIT; }

    uint32_t af[2][4][4], bf[2][NB][4];

    for (int kt = 0; kt < 32; ++kt) {
        if ((kt & 1) == 0) {
            CP_WAIT(AH - 2);
            __syncthreads();
        }
        const uint32_t as = sb + (kt % NS) * STG;
        const uint32_t bs = as + 16384;
        LD_FRAGS(0, as, bs, 0);          // LDSM latency hides under fill issue
        if (kt + AH < 32) { GF((kt + AH) % NS, kt + AH); }
        CP_COMMIT;
#pragma unroll
        for (int ks = 0; ks < 4; ++ks) {
            const int kc = ks & 1;
            if (ks < 3) LD_FRAGS(kc ^ 1, as, bs, ks + 1);
#pragma unroll
            for (int mt = 0; mt < 4; ++mt)
#pragma unroll
                for (int np = 0; np < NB; ++np) {
                    mma_f16(acc[mt][2 * np],     af[kc][mt], bf[kc][np][0], bf[kc][np][2]);
                    mma_f16(acc[mt][2 * np + 1], af[kc][mt], bf[kc][np][1], bf[kc][np][3]);
                }
        }
    }

    // epilogue
#pragma unroll
    for (int mt = 0; mt < 4; ++mt) {
        int r0 = bm + wm * 64 + mt * 16 + g;
#pragma unroll
        for (int nt = 0; nt < WN; ++nt) {
            int c = bn + wn * (8 * WN) + nt * 8 + 2 * tig;
            float b0 = bias[c], b1 = bias[c + 1];
            float v00 = acc[mt][nt][0] + b0, v01 = acc[mt][nt][1] + b1;
            float v10 = acc[mt][nt][2] + b0, v11 = acc[mt][nt][3] + b1;
            if (out_f32) {
                *(float2*)(Cf + (size_t)r0 * ldc + c) = make_float2(v00, v01);
                *(float2*)(Cf + (size_t)(r0 + 8) * ldc + c) = make_float2(v10, v11);
            } else {
                __half2 h0 = __floats2half2_rn(v00, v01);
                __half2 h1 = __floats2half2_rn(v10, v11);
                *(__half2*)(Ch + (size_t)r0 * ldc + c) = h0;
                *(__half2*)(Ch + (size_t)(r0 + 8) * ldc + c) = h1;
            }
        }
    }
#undef GF
#undef LD_FRAGS
}

// ---------------------------------------------------------------------------
// Fused RMSNorm+RoPE for BOTH Q and K (blockIdx.y selects), trig from table.
// ---------------------------------------------------------------------------
__global__ __launch_bounds__(256) void rmsnorm_rope_h(
    __half* __restrict__ qkv, const float* __restrict__ gq,
    const float* __restrict__ gk, const float2* __restrict__ trig)
{
    const int row = blockIdx.x;
    const int s = row & (S - 1);
    const int tid = threadIdx.x;
    const float* gw = blockIdx.y ? gk : gq;
    __half* p = qkv + (size_t)row * N_QKV + blockIdx.y * D;

    uint4 raw = *(const uint4*)(p + tid * 8);
    __half2 h[4] = { *(__half2*)&raw.x, *(__half2*)&raw.y,
                     *(__half2*)&raw.z, *(__half2*)&raw.w };
    float u[8];
#pragma unroll
    for (int j = 0; j < 4; ++j) {
        float2 f = __half22float2(h[j]);
        u[2 * j] = f.x; u[2 * j + 1] = f.y;
    }
    float ss = 0.f;
#pragma unroll
    for (int j = 0; j < 8; ++j) ss += u[j] * u[j];

    __shared__ float red[256];
    red[tid] = ss;
    __syncthreads();
    for (int off = 128; off > 0; off >>= 1) {
        if (tid < off) red[tid] += red[tid + off];
        __syncthreads();
    }
    const float inv = rsqrtf(red[0] / (float)D + 1e-6f);

    float4 g0 = *(const float4*)(gw + tid * 8);
    float4 g1 = *(const float4*)(gw + tid * 8 + 4);
    u[0] *= inv * g0.x; u[1] *= inv * g0.y; u[2] *= inv * g0.z; u[3] *= inv * g0.w;
    u[4] *= inv * g1.x; u[5] *= inv * g1.y; u[6] *= inv * g1.z; u[7] *= inv * g1.w;

    uint4 outw;
    uint32_t* ow = (uint32_t*)&outw;
#pragma unroll
    for (int j = 0; j < 4; ++j) {
        int pidx = tid * 4 + j;
        int i = pidx & 63;
        float2 cs = trig[(size_t)s * 64 + i];
        float re = u[2 * j], im = u[2 * j + 1];
        __half2 hv = __floats2half2_rn(re * cs.x - im * cs.y, re * cs.y + im * cs.x);
        ow[j] = *(uint32_t*)&hv;
    }
    *(uint4*)(p + tid * 8) = outw;
}

// ---------------------------------------------------------------------------
// Flash attention fp16, 5-stage K/V pipeline with even-iteration barriers.
// smem: K 5 stages [0,81920), V 5 stages [81920,163840), P [163840,180224).
// ---------------------------------------------------------------------------
#define FA_SMEM_BYTES 180224

__global__ __launch_bounds__(256) void flash_f16(
    const __half* __restrict__ QKV, const int* __restrict__ seq_lens,
    __half* __restrict__ Og)
{
    extern __shared__ char smf[];
    const uint32_t sb = (uint32_t)__cvta_generic_to_shared(smf);
    const int tid = threadIdx.x, lane = tid & 31, w = tid >> 5;
    const int g = lane >> 2, tig = lane & 3;
    const int bh = blockIdx.y, b = bh >> 4, h = bh & 15;
    const int q0 = blockIdx.x * 128;
    const int len = seq_lens[b];
    const float scale = 0.088388347648318447f;  // 1/sqrt(128)

    const __half* Qb = QKV + (size_t)b * S * N_QKV + h * HD;
    const __half* Kb = Qb + D;
    const __half* Vb = Qb + 2 * D;

    const int tl = lane >> 3, lr = lane & 7;
    const int rowoff = ((tl & 1) << 3) + lr;
    const int kadd = tl >> 1;
    const int fro = tid >> 4, fc16 = tid & 15;

#define KV_FILL(st, j0)                                                         \
    do {                                                                        \
        _Pragma("unroll")                                                       \
        for (int i = 0; i < 4; ++i) {                                           \
            int row = fro + 16 * i;                                             \
            uint32_t soff = (uint32_t)(row * 256 + ((fc16 ^ (row & 7)) << 4));  \
            cpa16(sb + (st) * 16384 + soff,                                     \
                  Kb + (size_t)((j0) + row) * N_QKV + fc16 * 8);                \
            cpa16(sb + 81920 + (st) * 16384 + soff,                             \
                  Vb + (size_t)((j0) + row) * N_QKV + fc16 * 8);                \
        }                                                                       \
    } while (0)

    KV_FILL(0, 0);   CP_COMMIT;
    KV_FILL(1, 64);  CP_COMMIT;
    KV_FILL(2, 128); CP_COMMIT;

    // Q fragments direct from gmem (rows w*16+g, w*16+g+8)
    uint32_t qf[8][4];
    {
        const __half* r0p = Qb + (size_t)(q0 + w * 16 + g) * N_QKV;
        const __half* r1p = r0p + (size_t)8 * N_QKV;
#pragma unroll
        for (int ks = 0; ks < 8; ++ks) {
            int c = ks * 16 + 2 * tig;
            qf[ks][0] = *(const uint32_t*)(r0p + c);
            qf[ks][1] = *(const uint32_t*)(r1p + c);
            qf[ks][2] = *(const uint32_t*)(r0p + c + 8);
            qf[ks][3] = *(const uint32_t*)(r1p + c + 8);
        }
    }

    float o[16][4];
#pragma unroll
    for (int nt = 0; nt < 16; ++nt)
#pragma unroll
        for (int e = 0; e < 4; ++e) o[nt][e] = 0.f;
    float m0 = -1e30f, m1 = -1e30f, l0 = 0.f, l1 = 0.f;

    const uint32_t pbase = sb + 163840;
    const int prA = w * 16 + g, prB = prA + 8;
    const uint32_t paddrA = pbase + prA * 128;
    const uint32_t paddrB = pbase + prB * 128;

    for (int t = 0; t < 32; ++t) {
        if ((t & 1) == 0) {
            CP_WAIT(1);
            __syncthreads();
        }
        if (t + 3 < 32) KV_FILL((t + 3) % 5, (t + 3) * 64);
        CP_COMMIT;
        const int st = t % 5;
        const uint32_t kst = sb + st * 16384;
        const uint32_t vst = sb + 81920 + st * 16384;

        // ---- S = Q @ K^T, kb double-buffered ----
        float s[8][4];
#pragma unroll
        for (int nt = 0; nt < 8; ++nt)
#pragma unroll
            for (int e = 0; e < 4; ++e) s[nt][e] = 0.f;

        uint32_t kb[2][4][4];
#define LD_KB(buf, ks)                                                          \
        do {                                                                    \
            const int c16 = 2 * (ks) + kadd;                                    \
            _Pragma("unroll")                                                   \
            for (int np = 0; np < 4; ++np) {                                    \
                int row = np * 16 + rowoff;                                     \
                ldm_x4(kb[buf][np], kst + row * 256 + ((c16 ^ (row & 7)) << 4));\
            }                                                                   \
        } while (0)

        LD_KB(0, 0);
#pragma unroll
        for (int ks = 0; ks < 8; ++ks) {
            const int kc = ks & 1;
            if (ks < 7) LD_KB(kc ^ 1, ks + 1);
#pragma unroll
            for (int np = 0; np < 4; ++np) {
                mma_f16(s[2 * np],     qf[ks], kb[kc][np][0], kb[kc][np][2]);
                mma_f16(s[2 * np + 1], qf[ks], kb[kc][np][1], kb[kc][np][3]);
            }
        }
#undef LD_KB

        const int j0 = t * 64;
        if (j0 + 64 > len) {
#pragma unroll
            for (int nt = 0; nt < 8; ++nt) {
                int c = j0 + nt * 8 + 2 * tig;
                if (c     >= len) { s[nt][0] = -1e30f; s[nt][2] = -1e30f; }
                if (c + 1 >= len) { s[nt][1] = -1e30f; s[nt][3] = -1e30f; }
            }
        }

        // ---- online softmax (rows g, g+8) ----
        float mx0 = -1e30f, mx1 = -1e30f;
#pragma unroll
        for (int nt = 0; nt < 8; ++nt) {
            mx0 = fmaxf(mx0, fmaxf(s[nt][0], s[nt][1]));
            mx1 = fmaxf(mx1, fmaxf(s[nt][2], s[nt][3]));
        }
        mx0 = fmaxf(mx0, __shfl_xor_sync(0xffffffffu, mx0, 1));
        mx0 = fmaxf(mx0, __shfl_xor_sync(0xffffffffu, mx0, 2));
        mx1 = fmaxf(mx1, __shfl_xor_sync(0xffffffffu, mx1, 1));
        mx1 = fmaxf(mx1, __shfl_xor_sync(0xffffffffu, mx1, 2));
        float mn0 = fmaxf(m0, mx0), mn1 = fmaxf(m1, mx1);
        float al0 = __expf(scale * (m0 - mn0));
        float al1 = __expf(scale * (m1 - mn1));
        float sum0 = 0.f, sum1 = 0.f;
#pragma unroll
        for (int nt = 0; nt < 8; ++nt) {
            s[nt][0] = __expf(scale * (s[nt][0] - mn0)); sum0 += s[nt][0];
            s[nt][1] = __expf(scale * (s[nt][1] - mn0)); sum0 += s[nt][1];
            s[nt][2] = __expf(scale * (s[nt][2] - mn1)); sum1 += s[nt][2];
            s[nt][3] = __expf(scale * (s[nt][3] - mn1)); sum1 += s[nt][3];
        }
        sum0 += __shfl_xor_sync(0xffffffffu, sum0, 1);
        sum0 += __shfl_xor_sync(0xffffffffu, sum0, 2);
        sum1 += __shfl_xor_sync(0xffffffffu, sum1, 1);
        sum1 += __shfl_xor_sync(0xffffffffu, sum1, 2);
        l0 = l0 * al0 + sum0; l1 = l1 * al1 + sum1;
        m0 = mn0; m1 = mn1;
#pragma unroll
        for (int nt = 0; nt < 16; ++nt) {
            o[nt][0] *= al0; o[nt][1] *= al0;
            o[nt][2] *= al1; o[nt][3] *= al1;
        }

        // ---- P -> per-warp smem (fp16) ----
#pragma unroll
        for (int nt = 0; nt < 8; ++nt) {
            __half2 hA = __floats2half2_rn(s[nt][0], s[nt][1]);
            __half2 hB = __floats2half2_rn(s[nt][2], s[nt][3]);
            uint32_t offA = ((nt ^ (prA & 7)) << 4) + 4 * tig;
            uint32_t offB = ((nt ^ (prB & 7)) << 4) + 4 * tig;
            *(uint32_t*)((char*)smf + (paddrA - sb) + offA) = *(uint32_t*)&hA;
            *(uint32_t*)((char*)smf + (paddrB - sb) + offB) = *(uint32_t*)&hB;
        }
        __syncwarp();

        // ---- O += P @ V, pa/vb double-buffered ----
        uint32_t pa[2][4], vb[2][4];
#define LD_PA(buf, ks)                                                          \
        do {                                                                    \
            int row = w * 16 + rowoff;                                          \
            int c16 = 2 * (ks) + kadd;                                          \
            ldm_x4(pa[buf], pbase + row * 128 + ((c16 ^ (row & 7)) << 4));      \
        } while (0)
#define LD_VB(buf, ks, np)                                                      \
        do {                                                                    \
            int row = (ks) * 16 + rowoff;                                       \
            int c16 = 2 * (np) + kadd;                                          \
            ldm_x4t(vb[buf], vst + row * 256 + ((c16 ^ (row & 7)) << 4));       \
        } while (0)

        LD_PA(0, 0);
        LD_VB(0, 0, 0);
#pragma unroll
        for (int ks = 0; ks < 4; ++ks) {
            const int pc = ks & 1;
            if (ks < 3) LD_PA(pc ^ 1, ks + 1);
#pragma unroll
            for (int np = 0; np < 8; ++np) {
                const int vc = np & 1;
                if (np < 7)       LD_VB(vc ^ 1, ks, np + 1);
                else if (ks < 3)  LD_VB(vc ^ 1, ks + 1, 0);
                mma_f16(o[2 * np],     pa[pc], vb[vc][0], vb[vc][1]);
                mma_f16(o[2 * np + 1], pa[pc], vb[vc][2], vb[vc][3]);
            }
        }
#undef LD_PA
#undef LD_VB
    }

    // ---- epilogue: normalize, store fp16 (row stride D) ----
    float li0 = 1.0f / l0, li1 = 1.0f / l1;
    __half* ObA = Og + (size_t)(b * S + q0 + w * 16 + g) * D + h * HD;
    __half* ObB = ObA + (size_t)8 * D;
#pragma unroll
    for (int nt = 0; nt < 16; ++nt) {
        int c = nt * 8 + 2 * tig;
        __half2 h0 = __floats2half2_rn(o[nt][0] * li0, o[nt][1] * li0);
        __half2 h1 = __floats2half2_rn(o[nt][2] * li1, o[nt][3] * li1);
        *(__half2*)(ObA + c) = h0;
        *(__half2*)(ObB + c) = h1;
    }
#undef KV_FILL
}

// ---------------------------------------------------------------------------
extern "C" void kernel_launch(void* const* d_in, const int* in_sizes, int n_in,
                              void* d_out, int out_size) {
    (void)in_sizes; (void)n_in; (void)out_size;
    const float* x        = (const float*)d_in[0];
    const int*   seq_lens = (const int*)  d_in[1];
    const float* freqs    = (const float*)d_in[2];
    const float* wq       = (const float*)d_in[3];
    const float* bq       = (const float*)d_in[4];
    const float* wk       = (const float*)d_in[5];
    const float* bk       = (const float*)d_in[6];
    const float* wv       = (const float*)d_in[7];
    const float* bv       = (const float*)d_in[8];
    const float* wo       = (const float*)d_in[9];
    const float* bo       = (const float*)d_in[10];
    const float* gq       = (const float*)d_in[11];
    const float* gk       = (const float*)d_in[12];
    float* out = (float*)d_out;

    __half *pxh, *pwh, *pqkv, *po;
    float* pbias;
    float2* ptrig;
    cudaGetSymbolAddress((void**)&pxh, g_xh);
    cudaGetSymbolAddress((void**)&pwh, g_wh);
    cudaGetSymbolAddress((void**)&pqkv, g_qkv);
    cudaGetSymbolAddress((void**)&po, g_oh);
    cudaGetSymbolAddress((void**)&pbias, g_bias);
    cudaGetSymbolAddress((void**)&ptrig, g_trig);
    __half* pw3 = pwh + 3 * (size_t)D * D;      // wo

    // QKV: WN=4, NWN=6 -> tile 128x192, 384 threads (12 warps, 3/SMSP)
    cudaFuncSetAttribute(gemm_f16<4, 6, 5, 3>,
                         cudaFuncAttributeMaxDynamicSharedMemorySize,
                         GEMM_SMEM_B(4, 6, 5));
    // O-proj: WN=8, NWN=4 -> tile 128x256, 256 threads (8 warps)
    cudaFuncSetAttribute(gemm_f16<8, 4, 4, 2>,
                         cudaFuncAttributeMaxDynamicSharedMemorySize,
                         GEMM_SMEM_B(8, 4, 4));
    cudaFuncSetAttribute(flash_f16, cudaFuncAttributeMaxDynamicSharedMemorySize,
                         FA_SMEM_BYTES);

    // preamble
    trig_k<<<S * 64 / 256, 256>>>(freqs, ptrig);
    conv_h<<<592, 256>>>(x, pxh, M_ROWS * D / 4);
    conv_w4<<<592, 256>>>(wq, wk, wv, wo, bq, bk, bv, pwh, pbias);
    // fused QKV projection
    gemm_f16<4, 6, 5, 3><<<dim3(N_QKV / 192, M_ROWS / 128), 384,
                           GEMM_SMEM_B(4, 6, 5)>>>(
        pxh, pwh, pbias, pqkv, nullptr, 0, N_QKV);
    // Q and K rmsnorm+rope
    rmsnorm_rope_h<<<dim3(M_ROWS, 2), 256>>>(pqkv, gq, gk, ptrig);
    // flash attention
    flash_f16<<<dim3(S / 128, B * NH), 256, FA_SMEM_BYTES>>>(
        pqkv, seq_lens, po);
    // output projection
    gemm_f16<8, 4, 4, 2><<<dim3(D / 256, M_ROWS / 128), 256,
                           GEMM_SMEM_B(8, 4, 4)>>>(
        po, pw3, bo, nullptr, out, 1, D);
}